// round 8
// baseline (speedup 1.0000x reference)
#include <cuda_runtime.h>
#include <math.h>
#include <stdint.h>

// Problem constants
#define Bn    128
#define Sn    256
#define Dn    256
#define Hn    6
#define HSn   42
#define HC    252        // Hn*HSn
#define NQKVP 768        // 3*HC = 756, padded to 768 for tile-exact GEMM
#define DFFn  1024
#define Mrows 32768      // Bn*Sn
#define BHn   (Bn*Hn)    // 768
#define PQ    52         // q/k per-row pitch (words): 42 data + 6 zero (to 48) + 4
#define PV    56         // v per-row pitch

// ---------------------------------------------------------------------------
// Scratch (allocation-free: __device__ globals)
// ---------------------------------------------------------------------------
__device__ uint32_t g_qT [(size_t)BHn * Sn * PQ];  // tf32 bits, [bh][s][52]
__device__ uint32_t g_kT [(size_t)BHn * Sn * PQ];
__device__ uint32_t g_vT [(size_t)BHn * Sn * PV];  // [bh][s][56]
__device__ float  g_heads[(size_t)Mrows * Dn];     // head_cat (cols 252..255 = 0)
__device__ float  g_res1 [(size_t)Mrows * Dn];
__device__ float  g_ln1  [(size_t)Mrows * Dn];
__device__ float  g_ff1  [(size_t)Mrows * DFFn];
__device__ float  g_res2 [(size_t)Mrows * Dn];
__device__ float  g_wqkv [Dn * NQKVP];
__device__ float  g_wproj[Dn * Dn];

// ---------------------------------------------------------------------------
// tf32 helpers
// ---------------------------------------------------------------------------
__device__ __forceinline__ uint32_t f2tf(float f) {
    uint32_t u;
    asm("cvt.rna.tf32.f32 %0, %1;" : "=r"(u) : "f"(f));
    return u;
}
__device__ __forceinline__ void mma_tf32(float c[4], const uint32_t a[4], const uint32_t b[2]) {
    asm volatile(
        "mma.sync.aligned.m16n8k8.row.col.f32.tf32.tf32.f32 "
        "{%0,%1,%2,%3}, {%4,%5,%6,%7}, {%8,%9}, {%0,%1,%2,%3};"
        : "+f"(c[0]), "+f"(c[1]), "+f"(c[2]), "+f"(c[3])
        : "r"(a[0]), "r"(a[1]), "r"(a[2]), "r"(a[3]), "r"(b[0]), "r"(b[1]));
}

// ---------------------------------------------------------------------------
// Weight packing + zero pads of qT/kT/vT (cols 42..) + zero g_heads pad cols
// ---------------------------------------------------------------------------
__global__ void pack_kernel(const float* __restrict__ Wq, const float* __restrict__ Wk,
                            const float* __restrict__ Wv, const float* __restrict__ Wproj,
                            float* __restrict__ wqkv, float* __restrict__ wproj_p,
                            float* __restrict__ heads,
                            uint32_t* __restrict__ qT, uint32_t* __restrict__ kT,
                            uint32_t* __restrict__ vT) {
    int idx = blockIdx.x * 256 + threadIdx.x;
    if (idx < Dn * NQKVP) {
        int d = idx / NQKVP, j = idx % NQKVP;
        float val = 0.0f;
        if (j < 756) {
            int which = j / HC;
            int rr = j - which * HC;
            int h = rr / HSn, c = rr - h * HSn;
            const float* W = (which == 0) ? Wq : (which == 1) ? Wk : Wv;
            val = W[(h * Dn + d) * HSn + c];
        }
        wqkv[idx] = val;
    }
    if (idx < Dn * Dn) {
        int rr = idx / Dn, c = idx % Dn;
        wproj_p[idx] = (rr < HC) ? Wproj[rr * Dn + c] : 0.0f;
    }
    if (idx < Mrows)
        *(float4*)&heads[(size_t)idx * Dn + 252] = make_float4(0.f, 0.f, 0.f, 0.f);
    // one thread per (bh, s) row: zero pad words
    {
        uint32_t* q = qT + (size_t)idx * PQ + HSn;
        uint32_t* k = kT + (size_t)idx * PQ + HSn;
        uint32_t* v = vT + (size_t)idx * PV + HSn;
#pragma unroll
        for (int i = 0; i < PQ - HSn; i++) { q[i] = 0u; k[i] = 0u; }
#pragma unroll
        for (int i = 0; i < PV - HSn; i++) v[i] = 0u;
    }
}

// ---------------------------------------------------------------------------
// tf32 tensor-core GEMM: C[M,N] = A[M,K] @ B[K,N] (+ epilogue)
// BM=128, BN=128, BK=16; 256 threads = 8 warps (2m x 4n), warp tile 64x32.
// MODE 0: raw; MODE 1: relu(acc+bias); MODE 2: acc+bias+resid
// MODE 3: QKV scatter -> g_qT/g_kT/g_vT as tf32 bits (C=qT, bias=kT, resid=vT)
// ---------------------------------------------------------------------------
#define LDA 20    // A smem pitch (16 + 4)
#define LDB 136   // B smem pitch (128 + 8)

template<int MODE>
__global__ __launch_bounds__(256) void gemm_tc(
    const float* __restrict__ A, const float* __restrict__ B, float* __restrict__ C,
    const float* __restrict__ bias, const float* __restrict__ resid,
    int M, int N, int K)
{
    __shared__ uint32_t As[2][128 * LDA];
    __shared__ uint32_t Bs[2][16 * LDB];

    int tid  = threadIdx.x;
    int lane = tid & 31, wid = tid >> 5;
    int wm = wid & 1, wn = wid >> 1;          // 2m x 4n warps
    int bm = blockIdx.y * 128, bn = blockIdx.x * 128;
    int r  = lane >> 2, cq = lane & 3;

    float acc[4][4][4];
#pragma unroll
    for (int mf = 0; mf < 4; mf++)
#pragma unroll
        for (int nf = 0; nf < 4; nf++)
#pragma unroll
            for (int i = 0; i < 4; i++) acc[mf][nf][i] = 0.0f;

    int a_r = tid >> 2;
    int a_c = (tid & 3) << 2;
    int b_r0 = tid >> 5;
    int b_r1 = b_r0 + 8;
    int b_c = (tid & 31) << 2;

    const float* Ag0 = A + (size_t)(bm + a_r) * K + a_c;
    const float* Ag1 = A + (size_t)(bm + a_r + 64) * K + a_c;
    const float* Bg0 = B + (size_t)b_r0 * N + bn + b_c;
    const float* Bg1 = B + (size_t)b_r1 * N + bn + b_c;

    float4 ra0, ra1, rb0, rb1;
    ra0 = *(const float4*)(Ag0);
    ra1 = *(const float4*)(Ag1);
    rb0 = *(const float4*)(Bg0);
    rb1 = *(const float4*)(Bg1);
    {
        uint4 u0 = make_uint4(f2tf(ra0.x), f2tf(ra0.y), f2tf(ra0.z), f2tf(ra0.w));
        uint4 u1 = make_uint4(f2tf(ra1.x), f2tf(ra1.y), f2tf(ra1.z), f2tf(ra1.w));
        uint4 v0 = make_uint4(f2tf(rb0.x), f2tf(rb0.y), f2tf(rb0.z), f2tf(rb0.w));
        uint4 v1 = make_uint4(f2tf(rb1.x), f2tf(rb1.y), f2tf(rb1.z), f2tf(rb1.w));
        *(uint4*)&As[0][a_r * LDA + a_c]        = u0;
        *(uint4*)&As[0][(a_r + 64) * LDA + a_c] = u1;
        *(uint4*)&Bs[0][b_r0 * LDB + b_c]       = v0;
        *(uint4*)&Bs[0][b_r1 * LDB + b_c]       = v1;
    }
    __syncthreads();

    int nk = K >> 4;
    for (int it = 0; it < nk; it++) {
        int cur = it & 1, nxt = cur ^ 1;
        bool more = (it + 1 < nk);
        if (more) {
            int k0 = (it + 1) << 4;
            ra0 = *(const float4*)(Ag0 + k0);
            ra1 = *(const float4*)(Ag1 + k0);
            rb0 = *(const float4*)(Bg0 + (size_t)k0 * N);
            rb1 = *(const float4*)(Bg1 + (size_t)k0 * N);
        }
#pragma unroll
        for (int kk = 0; kk < 16; kk += 8) {
            uint32_t a[4][4], b[4][2];
#pragma unroll
            for (int mf = 0; mf < 4; mf++) {
                int ar = (wm * 64 + mf * 16 + r) * LDA + kk + cq;
                a[mf][0] = As[cur][ar];
                a[mf][1] = As[cur][ar + 8 * LDA];
                a[mf][2] = As[cur][ar + 4];
                a[mf][3] = As[cur][ar + 8 * LDA + 4];
            }
#pragma unroll
            for (int nf = 0; nf < 4; nf++) {
                int bc = (kk + cq) * LDB + wn * 32 + nf * 8 + r;
                b[nf][0] = Bs[cur][bc];
                b[nf][1] = Bs[cur][bc + 4 * LDB];
            }
#pragma unroll
            for (int mf = 0; mf < 4; mf++)
#pragma unroll
                for (int nf = 0; nf < 4; nf++)
                    mma_tf32(acc[mf][nf], a[mf], b[nf]);
        }
        if (more) {
            uint4 u0 = make_uint4(f2tf(ra0.x), f2tf(ra0.y), f2tf(ra0.z), f2tf(ra0.w));
            uint4 u1 = make_uint4(f2tf(ra1.x), f2tf(ra1.y), f2tf(ra1.z), f2tf(ra1.w));
            uint4 v0 = make_uint4(f2tf(rb0.x), f2tf(rb0.y), f2tf(rb0.z), f2tf(rb0.w));
            uint4 v1 = make_uint4(f2tf(rb1.x), f2tf(rb1.y), f2tf(rb1.z), f2tf(rb1.w));
            *(uint4*)&As[nxt][a_r * LDA + a_c]        = u0;
            *(uint4*)&As[nxt][(a_r + 64) * LDA + a_c] = u1;
            *(uint4*)&Bs[nxt][b_r0 * LDB + b_c]       = v0;
            *(uint4*)&Bs[nxt][b_r1 * LDB + b_c]       = v1;
        }
        __syncthreads();
    }

#pragma unroll
    for (int mf = 0; mf < 4; mf++) {
#pragma unroll
        for (int nf = 0; nf < 4; nf++) {
            int row = bm + wm * 64 + mf * 16 + r;
            int col = bn + wn * 32 + nf * 8 + cq * 2;
            if (MODE == 3) {
                if (col < 756) {
                    int which = col / HC;
                    int rem = col - which * HC;
                    int h = rem / HSn;
                    int d = rem - h * HSn;
                    int b = row >> 8, s = row & 255;
                    int bh = b * Hn + h;
                    uint32_t* dst = (which == 0) ? (uint32_t*)C
                                  : (which == 1) ? (uint32_t*)(size_t)bias
                                                 : (uint32_t*)(size_t)resid;
                    int pitch = (which == 2) ? PV : PQ;
                    size_t i0 = ((size_t)bh * Sn + s) * pitch + d;
                    size_t i1 = ((size_t)bh * Sn + s + 8) * pitch + d;
                    *(uint2*)&dst[i0] = make_uint2(f2tf(acc[mf][nf][0]), f2tf(acc[mf][nf][1]));
                    *(uint2*)&dst[i1] = make_uint2(f2tf(acc[mf][nf][2]), f2tf(acc[mf][nf][3]));
                }
            } else {
                float v0 = acc[mf][nf][0], v1 = acc[mf][nf][1];
                float v2 = acc[mf][nf][2], v3 = acc[mf][nf][3];
                size_t o0 = (size_t)row * N + col;
                size_t o1 = (size_t)(row + 8) * N + col;
                if (MODE == 1) {
                    float b0 = bias[col], b1 = bias[col + 1];
                    v0 = fmaxf(v0 + b0, 0.f); v1 = fmaxf(v1 + b1, 0.f);
                    v2 = fmaxf(v2 + b0, 0.f); v3 = fmaxf(v3 + b1, 0.f);
                }
                if (MODE == 2) {
                    float b0 = bias[col], b1 = bias[col + 1];
                    float2 r0 = *(const float2*)(resid + o0);
                    float2 r1 = *(const float2*)(resid + o1);
                    v0 += b0 + r0.x; v1 += b1 + r0.y;
                    v2 += b0 + r1.x; v3 += b1 + r1.y;
                }
                *(float2*)(C + o0) = make_float2(v0, v1);
                *(float2*)(C + o1) = make_float2(v2, v3);
            }
        }
    }
}

// ---------------------------------------------------------------------------
// Fused causal attention v3: one block per (b, h, mtile). 512 threads.
// Inputs are pre-transposed, pre-tf32, pitch-matched -> smem fill is a pure
// uint4 memcpy (coalesced, high MLP, zero index math, zero cvt).
// Softmax via Cauchy-Schwarz bound (scale folded into exp).
// ---------------------------------------------------------------------------
#define LP  132
#define ATTN_SMEM ((128*PQ + 256*PQ + 128*PV + 128*LP) * 4 + (128 + 128 + 16) * 4)

__global__ __launch_bounds__(512) void attn_fused(const uint32_t* __restrict__ qT,
                                                  const uint32_t* __restrict__ kT,
                                                  const uint32_t* __restrict__ vT,
                                                  float* __restrict__ heads) {
    extern __shared__ uint32_t smu[];
    uint32_t* Qs = smu;                    // [128][PQ]
    uint32_t* Ks = Qs + 128 * PQ;          // [256][PQ]
    uint32_t* Vs = Ks + 256 * PQ;          // [128][PV]
    uint32_t* Ps = Vs + 128 * PV;          // [128][LP]
    float* lrow = (float*)(Ps + 128 * LP); // [128]
    float* m0s  = lrow + 128;              // [128]
    float* red  = m0s + 128;               // [16]

    int bh = blockIdx.x;
    int b = bh / Hn, h = bh - b * Hn;
    int mtile = blockIdx.y;
    int bm = mtile * 128;
    int nkeys = bm + 128;

    int tid = threadIdx.x, lane = tid & 31, wid = tid >> 5;
    int r = lane >> 2, cq = lane & 3;
    const float scale = rsqrtf(42.0f);

    // ---- Phase A: straight uint4 copies ----
    {
        const uint4* qg = (const uint4*)(qT + ((size_t)bh * Sn + bm) * PQ);
        uint4* qs = (uint4*)Qs;
#pragma unroll 4
        for (int i = tid; i < 128 * (PQ / 4); i += 512) qs[i] = qg[i];

        const uint4* kg = (const uint4*)(kT + (size_t)bh * Sn * PQ);
        uint4* ks = (uint4*)Ks;
        int nk4 = nkeys * (PQ / 4);
#pragma unroll 7
        for (int i = tid; i < nk4; i += 512) ks[i] = kg[i];
    }
    if (tid < 128) lrow[tid] = 0.f;
    __syncthreads();

    // kmax2 over |k_row|^2 (tf32 bits -> valid floats; pad cols are zero)
    float kn = 0.f;
    for (int rr = tid; rr < nkeys; rr += 512) {
        float s = 0.f;
#pragma unroll
        for (int c = 0; c < HSn; c++) {
            float v = __uint_as_float(Ks[rr * PQ + c]);
            s = fmaf(v, v, s);
        }
        kn = fmaxf(kn, s);
    }
#pragma unroll
    for (int off = 16; off > 0; off >>= 1)
        kn = fmaxf(kn, __shfl_xor_sync(0xffffffffu, kn, off));
    if (lane == 0) red[wid] = kn;
    __syncthreads();
    float kmax2 = red[0];
#pragma unroll
    for (int i = 1; i < 16; i++) kmax2 = fmaxf(kmax2, red[i]);
    if (tid < 128) {
        float qn = 0.f;
#pragma unroll
        for (int c = 0; c < HSn; c++) {
            float v = __uint_as_float(Qs[tid * PQ + c]);
            qn = fmaf(v, v, qn);
        }
        m0s[tid] = scale * sqrtf(qn * kmax2);   // >= all scaled scores of this row
    }

    float oacc[3][4];
#pragma unroll
    for (int nf = 0; nf < 3; nf++)
#pragma unroll
        for (int i = 0; i < 4; i++) oacc[nf][i] = 0.f;

    int wm = wid & 3, wn = wid >> 2;       // S-phase: 4m x 4n (32x32 tiles)
    int pm = wid & 7, pn = wid >> 3;       // PV-phase: 8 rows x 2 col-groups

    for (int kc = 0; kc <= mtile; kc++) {
        __syncthreads();   // Vs/Ps reusable; m0s ready (first iter)

        // load V chunk (pure copy)
        {
            const uint4* vg = (const uint4*)(vT + ((size_t)bh * Sn + kc * 128) * PV);
            uint4* vs = (uint4*)Vs;
#pragma unroll 4
            for (int i = tid; i < 128 * (PV / 4); i += 512) vs[i] = vg[i];
        }

        // S = Q @ K_chunk^T   (warp tile 32 x 32, k = 48)
        float sacc[2][4][4];
#pragma unroll
        for (int mf = 0; mf < 2; mf++)
#pragma unroll
            for (int nf = 0; nf < 4; nf++)
#pragma unroll
                for (int i = 0; i < 4; i++) sacc[mf][nf][i] = 0.f;

#pragma unroll
        for (int kk = 0; kk < 48; kk += 8) {
            uint32_t a[2][4], bf[4][2];
#pragma unroll
            for (int mf = 0; mf < 2; mf++) {
                int ar = (wm * 32 + mf * 16 + r) * PQ + kk + cq;
                a[mf][0] = Qs[ar];
                a[mf][1] = Qs[ar + 8 * PQ];
                a[mf][2] = Qs[ar + 4];
                a[mf][3] = Qs[ar + 8 * PQ + 4];
            }
#pragma unroll
            for (int nf = 0; nf < 4; nf++) {
                int bc = (kc * 128 + wn * 32 + nf * 8 + r) * PQ + kk + cq;
                bf[nf][0] = Ks[bc];
                bf[nf][1] = Ks[bc + 4];
            }
#pragma unroll
            for (int mf = 0; mf < 2; mf++)
#pragma unroll
                for (int nf = 0; nf < 4; nf++)
                    mma_tf32(sacc[mf][nf], a[mf], bf[nf]);
        }

        // p = exp(scale*s - m0) + causal mask; row sums; P -> smem (tf32)
#pragma unroll
        for (int mf = 0; mf < 2; mf++) {
            int lr0 = wm * 32 + mf * 16 + r;
            int lr1 = lr0 + 8;
            int gr0 = bm + lr0, gr1 = bm + lr1;
            float m00 = m0s[lr0], m01 = m0s[lr1];
            float rs0 = 0.f, rs1 = 0.f;
#pragma unroll
            for (int nf = 0; nf < 4; nf++) {
                int lc = wn * 32 + nf * 8 + cq * 2;
                int gc = kc * 128 + lc;
                float p00 = (gc     <= gr0) ? __expf(fmaf(scale, sacc[mf][nf][0], -m00)) : 0.f;
                float p01 = (gc + 1 <= gr0) ? __expf(fmaf(scale, sacc[mf][nf][1], -m00)) : 0.f;
                float p10 = (gc     <= gr1) ? __expf(fmaf(scale, sacc[mf][nf][2], -m01)) : 0.f;
                float p11 = (gc + 1 <= gr1) ? __expf(fmaf(scale, sacc[mf][nf][3], -m01)) : 0.f;
                rs0 += p00 + p01;
                rs1 += p10 + p11;
                *(uint2*)&Ps[lr0 * LP + lc] = make_uint2(f2tf(p00), f2tf(p01));
                *(uint2*)&Ps[lr1 * LP + lc] = make_uint2(f2tf(p10), f2tf(p11));
            }
            rs0 += __shfl_xor_sync(0xffffffffu, rs0, 1);
            rs0 += __shfl_xor_sync(0xffffffffu, rs0, 2);
            rs1 += __shfl_xor_sync(0xffffffffu, rs1, 1);
            rs1 += __shfl_xor_sync(0xffffffffu, rs1, 2);
            if (cq == 0) {
                atomicAdd(&lrow[lr0], rs0);
                atomicAdd(&lrow[lr1], rs1);
            }
        }
        __syncthreads();   // P + V visible

        // O += P @ V_chunk : warp tile 16 rows x 24 cols
#pragma unroll
        for (int kk = 0; kk < 128; kk += 8) {
            uint32_t a[4];
            int ar = (pm * 16 + r) * LP + kk + cq;
            a[0] = Ps[ar];
            a[1] = Ps[ar + 8 * LP];
            a[2] = Ps[ar + 4];
            a[3] = Ps[ar + 8 * LP + 4];
            uint32_t bf[3][2];
#pragma unroll
            for (int nf = 0; nf < 3; nf++) {
                int bc = (kk + cq) * PV + pn * 24 + nf * 8 + r;
                bf[nf][0] = Vs[bc];
                bf[nf][1] = Vs[bc + 4 * PV];
            }
#pragma unroll
            for (int nf = 0; nf < 3; nf++)
                mma_tf32(oacc[nf], a, bf[nf]);
        }
    }
    __syncthreads();

    // epilogue: divide by row sums, write to head_cat
    int lr0 = pm * 16 + r;
    int lr1 = lr0 + 8;
    float li0 = 1.0f / lrow[lr0];
    float li1 = 1.0f / lrow[lr1];
#pragma unroll
    for (int nf = 0; nf < 3; nf++) {
        int col = pn * 24 + nf * 8 + cq * 2;
        if (col < HSn) {
            *(float2*)&heads[(size_t)(b * Sn + bm + lr0) * Dn + h * HSn + col] =
                make_float2(oacc[nf][0] * li0, oacc[nf][1] * li0);
            *(float2*)&heads[(size_t)(b * Sn + bm + lr1) * Dn + h * HSn + col] =
                make_float2(oacc[nf][2] * li1, oacc[nf][3] * li1);
        }
    }
}

// ---------------------------------------------------------------------------
// LayerNorm over last dim (256): one warp per row.
// ---------------------------------------------------------------------------
__global__ void ln_kernel(const float* __restrict__ in, const float* __restrict__ g,
                          const float* __restrict__ bb, float* __restrict__ out) {
    int row = blockIdx.x * blockDim.y + threadIdx.y;
    int lane = threadIdx.x;
    const float4* x = (const float4*)(in + (size_t)row * Dn);
    float4 a = x[lane];
    float4 c = x[lane + 32];
    float s  = a.x + a.y + a.z + a.w + c.x + c.y + c.z + c.w;
    float ss = a.x*a.x + a.y*a.y + a.z*a.z + a.w*a.w
             + c.x*c.x + c.y*c.y + c.z*c.z + c.w*c.w;
#pragma unroll
    for (int off = 16; off > 0; off >>= 1) {
        s  += __shfl_xor_sync(0xffffffffu, s,  off);
        ss += __shfl_xor_sync(0xffffffffu, ss, off);
    }
    float mean = s * (1.0f / 256.0f);
    float var  = ss * (1.0f / 256.0f) - mean * mean;
    float rstd = rsqrtf(var + 1e-5f);
    float4 g1 = ((const float4*)g)[lane],  g2 = ((const float4*)g)[lane + 32];
    float4 b1 = ((const float4*)bb)[lane], b2 = ((const float4*)bb)[lane + 32];
    float4 r1, r2;
    r1.x = (a.x - mean) * rstd * g1.x + b1.x;
    r1.y = (a.y - mean) * rstd * g1.y + b1.y;
    r1.z = (a.z - mean) * rstd * g1.z + b1.z;
    r1.w = (a.w - mean) * rstd * g1.w + b1.w;
    r2.x = (c.x - mean) * rstd * g2.x + b2.x;
    r2.y = (c.y - mean) * rstd * g2.y + b2.y;
    r2.z = (c.z - mean) * rstd * g2.z + b2.z;
    r2.w = (c.w - mean) * rstd * g2.w + b2.w;
    float4* o4 = (float4*)(out + (size_t)row * Dn);
    o4[lane] = r1;
    o4[lane + 32] = r2;
}

// ---------------------------------------------------------------------------
// Launch
// ---------------------------------------------------------------------------
extern "C" void kernel_launch(void* const* d_in, const int* in_sizes, int n_in,
                              void* d_out, int out_size) {
    const float* x     = (const float*)d_in[0];
    const float* Wq    = (const float*)d_in[1];
    const float* Wk    = (const float*)d_in[2];
    const float* Wv    = (const float*)d_in[3];
    const float* Wproj = (const float*)d_in[4];
    const float* bproj = (const float*)d_in[5];
    const float* ln1_g = (const float*)d_in[6];
    const float* ln1_b = (const float*)d_in[7];
    const float* W1    = (const float*)d_in[8];
    const float* b1    = (const float*)d_in[9];
    const float* W2    = (const float*)d_in[10];
    const float* b2    = (const float*)d_in[11];
    const float* ln2_g = (const float*)d_in[12];
    const float* ln2_b = (const float*)d_in[13];
    float* out = (float*)d_out;

    float *heads, *res1, *ln1, *ff1, *res2, *wqkv, *wproj;
    uint32_t *qT, *kT, *vT;
    cudaGetSymbolAddress((void**)&qT,    g_qT);
    cudaGetSymbolAddress((void**)&kT,    g_kT);
    cudaGetSymbolAddress((void**)&vT,    g_vT);
    cudaGetSymbolAddress((void**)&heads, g_heads);
    cudaGetSymbolAddress((void**)&res1,  g_res1);
    cudaGetSymbolAddress((void**)&ln1,   g_ln1);
    cudaGetSymbolAddress((void**)&ff1,   g_ff1);
    cudaGetSymbolAddress((void**)&res2,  g_res2);
    cudaGetSymbolAddress((void**)&wqkv,  g_wqkv);
    cudaGetSymbolAddress((void**)&wproj, g_wproj);

    cudaFuncSetAttribute(attn_fused, cudaFuncAttributeMaxDynamicSharedMemorySize, ATTN_SMEM);

    // 1. pack weights (+ zero qT/kT/vT pad cols + head_cat pad cols)
    pack_kernel<<<768, 256>>>(Wq, Wk, Wv, Wproj, wqkv, wproj, heads, qT, kT, vT);
    // 2. QKV GEMM, scatter epilogue -> per-head tf32 tensors
    gemm_tc<3><<<dim3(NQKVP / 128, Mrows / 128), 256>>>(
        x, wqkv, (float*)qT, (const float*)kT, (const float*)vT, Mrows, NQKVP, Dn);
    // 3. fused attention -> head_cat
    attn_fused<<<dim3(BHn, 2), 512, ATTN_SMEM>>>(qT, kT, vT, heads);
    // 4. proj + residual(x)
    gemm_tc<2><<<dim3(Dn / 128, Mrows / 128), 256>>>(heads, wproj, res1, bproj, x, Mrows, Dn, Dn);
    // 5. LN1
    ln_kernel<<<Mrows / 8, dim3(32, 8)>>>(res1, ln1_g, ln1_b, ln1);
    // 6. FFN1 + ReLU
    gemm_tc<1><<<dim3(DFFn / 128, Mrows / 128), 256>>>(ln1, W1, ff1, b1, nullptr, Mrows, DFFn, Dn);
    // 7. FFN2 + residual(ln1)
    gemm_tc<2><<<dim3(Dn / 128, Mrows / 128), 256>>>(ff1, W2, res2, b2, ln1, Mrows, Dn, DFFn);
    // 8. LN2 -> output
    ln_kernel<<<Mrows / 8, dim3(32, 8)>>>(res2, ln2_g, ln2_b, out);
}

// round 9
// speedup vs baseline: 1.0835x; 1.0835x over previous
#include <cuda_runtime.h>
#include <math.h>
#include <stdint.h>

// Problem constants
#define Bn    128
#define Sn    256
#define Dn    256
#define Hn    6
#define HSn   42
#define HC    252
#define NQKVP 768
#define DFFn  1024
#define Mrows 32768
#define BHn   (Bn*Hn)

// ---------------------------------------------------------------------------
// Scratch (allocation-free: __device__ globals)
// ---------------------------------------------------------------------------
__device__ float    g_qkv  [(size_t)Mrows * NQKVP]; // fp32 q|k|v
__device__ uint32_t g_xt   [(size_t)Mrows * Dn];    // x as tf32 bits
__device__ uint32_t g_heads[(size_t)Mrows * Dn];    // head_cat as tf32 bits
__device__ float    g_res1 [(size_t)Mrows * Dn];
__device__ float    g_ln1  [(size_t)Mrows * Dn];    // LN1 out (fp32, resid use)
__device__ uint32_t g_ln1t [(size_t)Mrows * Dn];    // LN1 out (tf32 bits, GEMM use)
__device__ uint32_t g_ff1  [(size_t)Mrows * DFFn];  // relu(ffn1) as tf32 bits
__device__ float    g_res2 [(size_t)Mrows * Dn];
__device__ uint32_t g_wqkv [Dn * NQKVP];            // tf32 bits
__device__ uint32_t g_wproj[Dn * Dn];
__device__ uint32_t g_w1t  [Dn * DFFn];
__device__ uint32_t g_w2t  [DFFn * Dn];

// ---------------------------------------------------------------------------
// tf32 helpers
// ---------------------------------------------------------------------------
__device__ __forceinline__ uint32_t f2tf(float f) {
    uint32_t u;
    asm("cvt.rna.tf32.f32 %0, %1;" : "=r"(u) : "f"(f));
    return u;
}
__device__ __forceinline__ void mma_tf32(float c[4], const uint32_t a[4], const uint32_t b[2]) {
    asm volatile(
        "mma.sync.aligned.m16n8k8.row.col.f32.tf32.tf32.f32 "
        "{%0,%1,%2,%3}, {%4,%5,%6,%7}, {%8,%9}, {%0,%1,%2,%3};"
        : "+f"(c[0]), "+f"(c[1]), "+f"(c[2]), "+f"(c[3])
        : "r"(a[0]), "r"(a[1]), "r"(a[2]), "r"(a[3]), "r"(b[0]), "r"(b[1]));
}
__device__ __forceinline__ void cp16(uint32_t saddr, const void* g) {
    asm volatile("cp.async.ca.shared.global [%0], [%1], 16;" :: "r"(saddr), "l"(g));
}

// ---------------------------------------------------------------------------
// Pack: weights -> tf32 bits; x -> tf32 bits; zero heads pad cols.
// grid 1024 x 256 = 262144 threads.
// ---------------------------------------------------------------------------
__global__ void pack_kernel(const float* __restrict__ x,
                            const float* __restrict__ Wq, const float* __restrict__ Wk,
                            const float* __restrict__ Wv, const float* __restrict__ Wproj,
                            const float* __restrict__ W1, const float* __restrict__ W2,
                            uint32_t* __restrict__ wqkv, uint32_t* __restrict__ wproj_p,
                            uint32_t* __restrict__ w1t, uint32_t* __restrict__ w2t,
                            uint32_t* __restrict__ xt, uint32_t* __restrict__ heads) {
    int idx = blockIdx.x * 256 + threadIdx.x;
    if (idx < Dn * NQKVP) {
        int d = idx / NQKVP, j = idx % NQKVP;
        float val = 0.0f;
        if (j < 756) {
            int which = j / HC;
            int rr = j - which * HC;
            int h = rr / HSn, c = rr - h * HSn;
            const float* W = (which == 0) ? Wq : (which == 1) ? Wk : Wv;
            val = W[(h * Dn + d) * HSn + c];
        }
        wqkv[idx] = f2tf(val);
    }
    if (idx < Dn * Dn) {
        int rr = idx / Dn, c = idx % Dn;
        wproj_p[idx] = f2tf((rr < HC) ? Wproj[rr * Dn + c] : 0.0f);
    }
    w1t[idx] = f2tf(W1[idx]);            // Dn*DFFn == 262144 exactly
    w2t[idx] = f2tf(W2[idx]);            // DFFn*Dn == 262144 exactly
    if (idx < Mrows)
        *(uint4*)&heads[(size_t)idx * Dn + 252] = make_uint4(0u, 0u, 0u, 0u);
    // x -> tf32 bits, float4 grid-stride (Mrows*Dn/4 = 2097152 -> 8 iters)
    const float4* x4 = (const float4*)x;
    uint4* xt4 = (uint4*)xt;
    for (int i = idx; i < Mrows * Dn / 4; i += 262144) {
        float4 v = x4[i];
        xt4[i] = make_uint4(f2tf(v.x), f2tf(v.y), f2tf(v.z), f2tf(v.w));
    }
}

// ---------------------------------------------------------------------------
// tf32 GEMM v3: pure cp.async 3-stage pipeline, zero conversions in loop.
// A, B are pre-rounded tf32 bit arrays. BM=128, BN=128, BK=16; 256 threads,
// 8 warps (2m x 4n), warp tile 64x32.
// MODE 0: fp32 out; MODE 1: relu(acc+bias) -> tf32 bits out;
// MODE 2: acc+bias+resid -> fp32 out
// ---------------------------------------------------------------------------
#define LDA 20
#define LDB 136
#define STGW (128*LDA + 16*LDB)      // 4736 words per stage
#define GEMM_SMEM (3 * STGW * 4)     // 56832 B

template<int MODE>
__global__ __launch_bounds__(256) void gemm_tc(
    const uint32_t* __restrict__ A, const uint32_t* __restrict__ B, void* __restrict__ Cv,
    const float* __restrict__ bias, const float* __restrict__ resid,
    int M, int N, int K)
{
    extern __shared__ uint32_t sm[];
    uint32_t sbase = (uint32_t)__cvta_generic_to_shared(sm);

    int tid  = threadIdx.x;
    int lane = tid & 31, wid = tid >> 5;
    int wm = wid & 1, wn = wid >> 1;
    int bm = blockIdx.y * 128, bn = blockIdx.x * 128;
    int r  = lane >> 2, cq = lane & 3;

    float acc[4][4][4];
#pragma unroll
    for (int mf = 0; mf < 4; mf++)
#pragma unroll
        for (int nf = 0; nf < 4; nf++)
#pragma unroll
            for (int i = 0; i < 4; i++) acc[mf][nf][i] = 0.0f;

    int a_r = tid >> 2;
    int a_c = (tid & 3) << 2;
    int b_r0 = tid >> 5;
    int b_r1 = b_r0 + 8;
    int b_c = (tid & 31) << 2;

    const uint32_t* Ag0 = A + (size_t)(bm + a_r) * K + a_c;
    const uint32_t* Ag1 = A + (size_t)(bm + a_r + 64) * K + a_c;
    const uint32_t* Bg0 = B + (size_t)b_r0 * N + bn + b_c;
    const uint32_t* Bg1 = B + (size_t)b_r1 * N + bn + b_c;

    uint32_t sA0 = sbase + (a_r * LDA + a_c) * 4;
    uint32_t sA1 = sbase + ((a_r + 64) * LDA + a_c) * 4;
    uint32_t sB0 = sbase + (128 * LDA + b_r0 * LDB + b_c) * 4;
    uint32_t sB1 = sbase + (128 * LDA + b_r1 * LDB + b_c) * 4;

    int nk = K >> 4;

    // prologue: tiles 0 and 1
#pragma unroll
    for (int p = 0; p < 2; p++) {
        uint32_t off = p * (STGW * 4);
        cp16(sA0 + off, Ag0 + p * 16);
        cp16(sA1 + off, Ag1 + p * 16);
        cp16(sB0 + off, Bg0 + (size_t)(p * 16) * N);
        cp16(sB1 + off, Bg1 + (size_t)(p * 16) * N);
        asm volatile("cp.async.commit_group;" ::: "memory");
    }

    for (int it = 0; it < nk; it++) {
        int s = it % 3;
        asm volatile("cp.async.wait_group 1;" ::: "memory");
        __syncthreads();

        int nt = it + 2;
        if (nt < nk) {
            uint32_t off = (nt % 3) * (STGW * 4);
            cp16(sA0 + off, Ag0 + nt * 16);
            cp16(sA1 + off, Ag1 + nt * 16);
            cp16(sB0 + off, Bg0 + (size_t)(nt * 16) * N);
            cp16(sB1 + off, Bg1 + (size_t)(nt * 16) * N);
        }
        asm volatile("cp.async.commit_group;" ::: "memory");

        const uint32_t* As = sm + s * STGW;
        const uint32_t* Bs = As + 128 * LDA;
#pragma unroll
        for (int kk = 0; kk < 16; kk += 8) {
            uint32_t a[4][4], b[4][2];
#pragma unroll
            for (int mf = 0; mf < 4; mf++) {
                int ar = (wm * 64 + mf * 16 + r) * LDA + kk + cq;
                a[mf][0] = As[ar];
                a[mf][1] = As[ar + 8 * LDA];
                a[mf][2] = As[ar + 4];
                a[mf][3] = As[ar + 8 * LDA + 4];
            }
#pragma unroll
            for (int nf = 0; nf < 4; nf++) {
                int bc = (kk + cq) * LDB + wn * 32 + nf * 8 + r;
                b[nf][0] = Bs[bc];
                b[nf][1] = Bs[bc + 4 * LDB];
            }
#pragma unroll
            for (int mf = 0; mf < 4; mf++)
#pragma unroll
                for (int nf = 0; nf < 4; nf++)
                    mma_tf32(acc[mf][nf], a[mf], b[nf]);
        }
    }

#pragma unroll
    for (int mf = 0; mf < 4; mf++) {
#pragma unroll
        for (int nf = 0; nf < 4; nf++) {
            int row = bm + wm * 64 + mf * 16 + r;
            int col = bn + wn * 32 + nf * 8 + cq * 2;
            size_t o0 = (size_t)row * N + col;
            size_t o1 = (size_t)(row + 8) * N + col;
            float v0 = acc[mf][nf][0], v1 = acc[mf][nf][1];
            float v2 = acc[mf][nf][2], v3 = acc[mf][nf][3];
            if (MODE == 1) {
                float b0 = bias[col], b1 = bias[col + 1];
                v0 = fmaxf(v0 + b0, 0.f); v1 = fmaxf(v1 + b1, 0.f);
                v2 = fmaxf(v2 + b0, 0.f); v3 = fmaxf(v3 + b1, 0.f);
                uint32_t* C = (uint32_t*)Cv;
                *(uint2*)&C[o0] = make_uint2(f2tf(v0), f2tf(v1));
                *(uint2*)&C[o1] = make_uint2(f2tf(v2), f2tf(v3));
            } else {
                if (MODE == 2) {
                    float b0 = bias[col], b1 = bias[col + 1];
                    float2 r0 = *(const float2*)(resid + o0);
                    float2 r1 = *(const float2*)(resid + o1);
                    v0 += b0 + r0.x; v1 += b1 + r0.y;
                    v2 += b0 + r1.x; v3 += b1 + r1.y;
                }
                float* C = (float*)Cv;
                *(float2*)&C[o0] = make_float2(v0, v1);
                *(float2*)&C[o1] = make_float2(v2, v3);
            }
        }
    }
}

// ---------------------------------------------------------------------------
// Fused causal attention (round-7 version; epilogue stores tf32 bits).
// One block per (b, h, mtile), 512 threads / 16 warps, 177KB smem.
// ---------------------------------------------------------------------------
#define LQ  52
#define LVF 56
#define LP  132
#define ATTN_SMEM ((128*LQ + 256*LQ + 128*LVF + 128*LP) * 4 + (128 + 128 + 16) * 4)

__global__ __launch_bounds__(512) void attn_fused(const float* __restrict__ qkv,
                                                  uint32_t* __restrict__ heads) {
    extern __shared__ uint32_t smu[];
    uint32_t* Qs = smu;
    uint32_t* Ks = Qs + 128 * LQ;
    uint32_t* Vs = Ks + 256 * LQ;
    uint32_t* Ps = Vs + 128 * LVF;
    float* lrow = (float*)(Ps + 128 * LP);
    float* m0s  = lrow + 128;
    float* red  = m0s + 128;

    int bh = blockIdx.x;
    int b = bh / Hn, h = bh - b * Hn;
    int mtile = blockIdx.y;
    int bm = mtile * 128;
    int nkeys = bm + 128;

    int tid = threadIdx.x, lane = tid & 31, wid = tid >> 5;
    int r = lane >> 2, cq = lane & 3;
    const float scale = rsqrtf(42.0f);
    const float* base = qkv + (size_t)b * Sn * NQKVP;

    for (int idx = tid; idx < 128 * 48; idx += 512) {
        int rr = idx / 48, c = idx - rr * 48;
        float v = (c < HSn) ? base[(size_t)(bm + rr) * NQKVP + h * HSn + c] * scale : 0.f;
        Qs[rr * LQ + c] = f2tf(v);
    }
    for (int idx = tid; idx < nkeys * 48; idx += 512) {
        int rr = idx / 48, c = idx - rr * 48;
        float v = (c < HSn) ? base[(size_t)rr * NQKVP + HC + h * HSn + c] : 0.f;
        Ks[rr * LQ + c] = f2tf(v);
    }
    if (tid < 128) lrow[tid] = 0.f;
    __syncthreads();

    float kn = 0.f;
    for (int rr = tid; rr < nkeys; rr += 512) {
        float s = 0.f;
#pragma unroll
        for (int c = 0; c < HSn; c++) {
            float v = __uint_as_float(Ks[rr * LQ + c]);
            s = fmaf(v, v, s);
        }
        kn = fmaxf(kn, s);
    }
#pragma unroll
    for (int off = 16; off > 0; off >>= 1)
        kn = fmaxf(kn, __shfl_xor_sync(0xffffffffu, kn, off));
    if (lane == 0) red[wid] = kn;
    __syncthreads();
    float kmax2 = red[0];
#pragma unroll
    for (int i = 1; i < 16; i++) kmax2 = fmaxf(kmax2, red[i]);
    if (tid < 128) {
        float qn = 0.f;
#pragma unroll
        for (int c = 0; c < HSn; c++) {
            float v = __uint_as_float(Qs[tid * LQ + c]);
            qn = fmaf(v, v, qn);
        }
        m0s[tid] = sqrtf(qn * kmax2);
    }

    float oacc[3][4];
#pragma unroll
    for (int nf = 0; nf < 3; nf++)
#pragma unroll
        for (int i = 0; i < 4; i++) oacc[nf][i] = 0.f;

    int wm = wid & 3, wn = wid >> 2;
    int pm = wid & 7, pn = wid >> 3;

    for (int kc = 0; kc <= mtile; kc++) {
        __syncthreads();

        for (int idx = tid; idx < 128 * 48; idx += 512) {
            int rr = idx / 48, c = idx - rr * 48;
            float v = (c < HSn)
                ? base[(size_t)(kc * 128 + rr) * NQKVP + 2 * HC + h * HSn + c] : 0.f;
            Vs[rr * LVF + c] = f2tf(v);
        }

        float sacc[2][4][4];
#pragma unroll
        for (int mf = 0; mf < 2; mf++)
#pragma unroll
            for (int nf = 0; nf < 4; nf++)
#pragma unroll
                for (int i = 0; i < 4; i++) sacc[mf][nf][i] = 0.f;

#pragma unroll
        for (int kk = 0; kk < 48; kk += 8) {
            uint32_t a[2][4], bf[4][2];
#pragma unroll
            for (int mf = 0; mf < 2; mf++) {
                int ar = (wm * 32 + mf * 16 + r) * LQ + kk + cq;
                a[mf][0] = Qs[ar];
                a[mf][1] = Qs[ar + 8 * LQ];
                a[mf][2] = Qs[ar + 4];
                a[mf][3] = Qs[ar + 8 * LQ + 4];
            }
#pragma unroll
            for (int nf = 0; nf < 4; nf++) {
                int bc = (kc * 128 + wn * 32 + nf * 8 + r) * LQ + kk + cq;
                bf[nf][0] = Ks[bc];
                bf[nf][1] = Ks[bc + 4];
            }
#pragma unroll
            for (int mf = 0; mf < 2; mf++)
#pragma unroll
                for (int nf = 0; nf < 4; nf++)
                    mma_tf32(sacc[mf][nf], a[mf], bf[nf]);
        }

#pragma unroll
        for (int mf = 0; mf < 2; mf++) {
            int lr0 = wm * 32 + mf * 16 + r;
            int lr1 = lr0 + 8;
            int gr0 = bm + lr0, gr1 = bm + lr1;
            float m00 = m0s[lr0], m01 = m0s[lr1];
            float rs0 = 0.f, rs1 = 0.f;
#pragma unroll
            for (int nf = 0; nf < 4; nf++) {
                int lc = wn * 32 + nf * 8 + cq * 2;
                int gc = kc * 128 + lc;
                float p00 = (gc     <= gr0) ? __expf(sacc[mf][nf][0] - m00) : 0.f;
                float p01 = (gc + 1 <= gr0) ? __expf(sacc[mf][nf][1] - m00) : 0.f;
                float p10 = (gc     <= gr1) ? __expf(sacc[mf][nf][2] - m01) : 0.f;
                float p11 = (gc + 1 <= gr1) ? __expf(sacc[mf][nf][3] - m01) : 0.f;
                rs0 += p00 + p01;
                rs1 += p10 + p11;
                *(uint2*)&Ps[lr0 * LP + lc] = make_uint2(f2tf(p00), f2tf(p01));
                *(uint2*)&Ps[lr1 * LP + lc] = make_uint2(f2tf(p10), f2tf(p11));
            }
            rs0 += __shfl_xor_sync(0xffffffffu, rs0, 1);
            rs0 += __shfl_xor_sync(0xffffffffu, rs0, 2);
            rs1 += __shfl_xor_sync(0xffffffffu, rs1, 1);
            rs1 += __shfl_xor_sync(0xffffffffu, rs1, 2);
            if (cq == 0) {
                atomicAdd(&lrow[lr0], rs0);
                atomicAdd(&lrow[lr1], rs1);
            }
        }
        __syncthreads();

#pragma unroll
        for (int kk = 0; kk < 128; kk += 8) {
            uint32_t a[4];
            int ar = (pm * 16 + r) * LP + kk + cq;
            a[0] = Ps[ar];
            a[1] = Ps[ar + 8 * LP];
            a[2] = Ps[ar + 4];
            a[3] = Ps[ar + 8 * LP + 4];
            uint32_t bf[3][2];
#pragma unroll
            for (int nf = 0; nf < 3; nf++) {
                int bc = (kk + cq) * LVF + pn * 24 + nf * 8 + r;
                bf[nf][0] = Vs[bc];
                bf[nf][1] = Vs[bc + 4 * LVF];
            }
#pragma unroll
            for (int nf = 0; nf < 3; nf++)
                mma_tf32(oacc[nf], a, bf[nf]);
        }
    }
    __syncthreads();

    int lr0 = pm * 16 + r;
    int lr1 = lr0 + 8;
    float li0 = 1.0f / lrow[lr0];
    float li1 = 1.0f / lrow[lr1];
#pragma unroll
    for (int nf = 0; nf < 3; nf++) {
        int col = pn * 24 + nf * 8 + cq * 2;
        if (col < HSn) {
            *(uint2*)&heads[(size_t)(b * Sn + bm + lr0) * Dn + h * HSn + col] =
                make_uint2(f2tf(oacc[nf][0] * li0), f2tf(oacc[nf][1] * li0));
            *(uint2*)&heads[(size_t)(b * Sn + bm + lr1) * Dn + h * HSn + col] =
                make_uint2(f2tf(oacc[nf][2] * li1), f2tf(oacc[nf][3] * li1));
        }
    }
}

// ---------------------------------------------------------------------------
// LayerNorm over last dim (256): one warp per row. Optional tf32-bits copy.
// ---------------------------------------------------------------------------
__global__ void ln_kernel(const float* __restrict__ in, const float* __restrict__ g,
                          const float* __restrict__ bb, float* __restrict__ out,
                          uint32_t* __restrict__ outT) {
    int row = blockIdx.x * blockDim.y + threadIdx.y;
    int lane = threadIdx.x;
    const float4* x = (const float4*)(in + (size_t)row * Dn);
    float4 a = x[lane];
    float4 c = x[lane + 32];
    float s  = a.x + a.y + a.z + a.w + c.x + c.y + c.z + c.w;
    float ss = a.x*a.x + a.y*a.y + a.z*a.z + a.w*a.w
             + c.x*c.x + c.y*c.y + c.z*c.z + c.w*c.w;
#pragma unroll
    for (int off = 16; off > 0; off >>= 1) {
        s  += __shfl_xor_sync(0xffffffffu, s,  off);
        ss += __shfl_xor_sync(0xffffffffu, ss, off);
    }
    float mean = s * (1.0f / 256.0f);
    float var  = ss * (1.0f / 256.0f) - mean * mean;
    float rstd = rsqrtf(var + 1e-5f);
    float4 g1 = ((const float4*)g)[lane],  g2 = ((const float4*)g)[lane + 32];
    float4 b1 = ((const float4*)bb)[lane], b2 = ((const float4*)bb)[lane + 32];
    float4 r1, r2;
    r1.x = (a.x - mean) * rstd * g1.x + b1.x;
    r1.y = (a.y - mean) * rstd * g1.y + b1.y;
    r1.z = (a.z - mean) * rstd * g1.z + b1.z;
    r1.w = (a.w - mean) * rstd * g1.w + b1.w;
    r2.x = (c.x - mean) * rstd * g2.x + b2.x;
    r2.y = (c.y - mean) * rstd * g2.y + b2.y;
    r2.z = (c.z - mean) * rstd * g2.z + b2.z;
    r2.w = (c.w - mean) * rstd * g2.w + b2.w;
    float4* o4 = (float4*)(out + (size_t)row * Dn);
    o4[lane] = r1;
    o4[lane + 32] = r2;
    if (outT) {
        uint4* t4 = (uint4*)(outT + (size_t)row * Dn);
        t4[lane]      = make_uint4(f2tf(r1.x), f2tf(r1.y), f2tf(r1.z), f2tf(r1.w));
        t4[lane + 32] = make_uint4(f2tf(r2.x), f2tf(r2.y), f2tf(r2.z), f2tf(r2.w));
    }
}

// ---------------------------------------------------------------------------
// Launch
// ---------------------------------------------------------------------------
extern "C" void kernel_launch(void* const* d_in, const int* in_sizes, int n_in,
                              void* d_out, int out_size) {
    const float* x     = (const float*)d_in[0];
    const float* Wq    = (const float*)d_in[1];
    const float* Wk    = (const float*)d_in[2];
    const float* Wv    = (const float*)d_in[3];
    const float* Wproj = (const float*)d_in[4];
    const float* bproj = (const float*)d_in[5];
    const float* ln1_g = (const float*)d_in[6];
    const float* ln1_b = (const float*)d_in[7];
    const float* W1    = (const float*)d_in[8];
    const float* b1    = (const float*)d_in[9];
    const float* W2    = (const float*)d_in[10];
    const float* b2    = (const float*)d_in[11];
    const float* ln2_g = (const float*)d_in[12];
    const float* ln2_b = (const float*)d_in[13];
    float* out = (float*)d_out;

    float *qkv, *res1, *ln1, *res2;
    uint32_t *xt, *heads, *ln1t, *ff1, *wqkv, *wproj, *w1t, *w2t;
    cudaGetSymbolAddress((void**)&qkv,   g_qkv);
    cudaGetSymbolAddress((void**)&xt,    g_xt);
    cudaGetSymbolAddress((void**)&heads, g_heads);
    cudaGetSymbolAddress((void**)&res1,  g_res1);
    cudaGetSymbolAddress((void**)&ln1,   g_ln1);
    cudaGetSymbolAddress((void**)&ln1t,  g_ln1t);
    cudaGetSymbolAddress((void**)&ff1,   g_ff1);
    cudaGetSymbolAddress((void**)&res2,  g_res2);
    cudaGetSymbolAddress((void**)&wqkv,  g_wqkv);
    cudaGetSymbolAddress((void**)&wproj, g_wproj);
    cudaGetSymbolAddress((void**)&w1t,   g_w1t);
    cudaGetSymbolAddress((void**)&w2t,   g_w2t);

    cudaFuncSetAttribute(attn_fused, cudaFuncAttributeMaxDynamicSharedMemorySize, ATTN_SMEM);
    cudaFuncSetAttribute(gemm_tc<0>, cudaFuncAttributeMaxDynamicSharedMemorySize, GEMM_SMEM);
    cudaFuncSetAttribute(gemm_tc<1>, cudaFuncAttributeMaxDynamicSharedMemorySize, GEMM_SMEM);
    cudaFuncSetAttribute(gemm_tc<2>, cudaFuncAttributeMaxDynamicSharedMemorySize, GEMM_SMEM);

    // 1. pack: weights->tf32, x->tf32, zero heads pads
    pack_kernel<<<1024, 256>>>(x, Wq, Wk, Wv, Wproj, W1, W2,
                               wqkv, wproj, w1t, w2t, xt, heads);
    // 2. QKV GEMM -> fp32 qkv
    gemm_tc<0><<<dim3(NQKVP / 128, Mrows / 128), 256, GEMM_SMEM>>>(
        xt, wqkv, qkv, nullptr, nullptr, Mrows, NQKVP, Dn);
    // 3. fused attention -> heads (tf32 bits)
    attn_fused<<<dim3(BHn, 2), 512, ATTN_SMEM>>>(qkv, heads);
    // 4. proj + bias + residual(x) -> res1 (fp32)
    gemm_tc<2><<<dim3(Dn / 128, Mrows / 128), 256, GEMM_SMEM>>>(
        heads, wproj, res1, bproj, x, Mrows, Dn, Dn);
    // 5. LN1 -> ln1 (fp32) + ln1t (tf32 bits)
    ln_kernel<<<Mrows / 8, dim3(32, 8)>>>(res1, ln1_g, ln1_b, ln1, ln1t);
    // 6. FFN1 + ReLU -> ff1 (tf32 bits)
    gemm_tc<1><<<dim3(DFFn / 128, Mrows / 128), 256, GEMM_SMEM>>>(
        ln1t, w1t, ff1, b1, nullptr, Mrows, DFFn, Dn);
    // 7. FFN2 + bias + residual(ln1) -> res2 (fp32)
    gemm_tc<2><<<dim3(Dn / 128, Mrows / 128), 256, GEMM_SMEM>>>(
        ff1, w2t, res2, b2, ln1, Mrows, Dn, DFFn);
    // 8. LN2 -> output
    ln_kernel<<<Mrows / 8, dim3(32, 8)>>>(res2, ln2_g, ln2_b, out, nullptr);
}

// round 11
// speedup vs baseline: 1.3882x; 1.2811x over previous
#include <cuda_runtime.h>
#include <cuda_fp16.h>
#include <math.h>
#include <stdint.h>

// Problem constants
#define Bn    128
#define Sn    256
#define Dn    256
#define Hn    6
#define HSn   42
#define HC    252
#define NQKVP 768
#define DFFn  1024
#define Mrows 32768
#define BHn   (Bn*Hn)

// ---------------------------------------------------------------------------
// Scratch (allocation-free: __device__ globals)
// ---------------------------------------------------------------------------
__device__ float  g_qkv  [(size_t)Mrows * NQKVP]; // fp32 q|k|v (attention input)
__device__ __half g_xh   [(size_t)Mrows * Dn];    // x as fp16
__device__ __half g_heads[(size_t)Mrows * Dn];    // head_cat fp16 (cols 252..255 = 0)
__device__ float  g_res1 [(size_t)Mrows * Dn];
__device__ float  g_ln1  [(size_t)Mrows * Dn];    // LN1 fp32 (resid use)
__device__ __half g_ln1h [(size_t)Mrows * Dn];    // LN1 fp16 (GEMM use)
__device__ __half g_ff1  [(size_t)Mrows * DFFn];  // relu(ffn1) fp16
__device__ float  g_res2 [(size_t)Mrows * Dn];
// Weights, TRANSPOSED [N][K], fp16:
__device__ __half g_wqkvT [NQKVP * Dn];
__device__ __half g_wprojT[Dn * Dn];
__device__ __half g_w1T   [DFFn * Dn];
__device__ __half g_w2T   [Dn * DFFn];

// ---------------------------------------------------------------------------
// helpers
// ---------------------------------------------------------------------------
__device__ __forceinline__ uint32_t f2tf(float f) {
    uint32_t u;
    asm("cvt.rna.tf32.f32 %0, %1;" : "=r"(u) : "f"(f));
    return u;
}
__device__ __forceinline__ void mma_tf32(float c[4], const uint32_t a[4], const uint32_t b[2]) {
    asm volatile(
        "mma.sync.aligned.m16n8k8.row.col.f32.tf32.tf32.f32 "
        "{%0,%1,%2,%3}, {%4,%5,%6,%7}, {%8,%9}, {%0,%1,%2,%3};"
        : "+f"(c[0]), "+f"(c[1]), "+f"(c[2]), "+f"(c[3])
        : "r"(a[0]), "r"(a[1]), "r"(a[2]), "r"(a[3]), "r"(b[0]), "r"(b[1]));
}
__device__ __forceinline__ void mma_f16(float c[4], const uint32_t a[4], const uint32_t b[2]) {
    asm volatile(
        "mma.sync.aligned.m16n8k16.row.col.f32.f16.f16.f32 "
        "{%0,%1,%2,%3}, {%4,%5,%6,%7}, {%8,%9}, {%0,%1,%2,%3};"
        : "+f"(c[0]), "+f"(c[1]), "+f"(c[2]), "+f"(c[3])
        : "r"(a[0]), "r"(a[1]), "r"(a[2]), "r"(a[3]), "r"(b[0]), "r"(b[1]));
}
__device__ __forceinline__ void cp16(uint32_t saddr, const void* g) {
    asm volatile("cp.async.ca.shared.global [%0], [%1], 16;" :: "r"(saddr), "l"(g));
}

// ---------------------------------------------------------------------------
// Pack: weights -> fp16 transposed [N][K]; x -> fp16; zero heads pad cols.
// grid 1024 x 256 = 262144 threads.
// ---------------------------------------------------------------------------
__global__ void pack_kernel(const float* __restrict__ x,
                            const float* __restrict__ Wq, const float* __restrict__ Wk,
                            const float* __restrict__ Wv, const float* __restrict__ Wproj,
                            const float* __restrict__ W1, const float* __restrict__ W2,
                            __half* __restrict__ wqkvT, __half* __restrict__ wprojT,
                            __half* __restrict__ w1T, __half* __restrict__ w2T,
                            __half* __restrict__ xh, __half* __restrict__ heads) {
    int idx = blockIdx.x * 256 + threadIdx.x;
    if (idx < NQKVP * Dn) {                 // wqkvT[j][d], j = output col
        int j = idx >> 8, d = idx & 255;
        float val = 0.0f;
        if (j < 756) {
            int which = j / HC;
            int rr = j - which * HC;
            int h = rr / HSn, c = rr - h * HSn;
            const float* W = (which == 0) ? Wq : (which == 1) ? Wk : Wv;
            val = W[(h * Dn + d) * HSn + c];
        }
        wqkvT[idx] = __float2half_rn(val);
    }
    if (idx < Dn * Dn) {                    // wprojT[n][k]
        int n = idx >> 8, k = idx & 255;
        wprojT[idx] = __float2half_rn((k < HC) ? Wproj[k * Dn + n] : 0.0f);
    }
    {                                       // w1T[n][k]: n = idx>>8 (0..1023), k = idx&255
        int n = idx >> 8, k = idx & 255;
        w1T[idx] = __float2half_rn(W1[k * DFFn + n]);
    }
    {                                       // w2T[n][k]: n = idx>>10 (0..255), k = idx&1023
        int n = idx >> 10, k = idx & 1023;
        w2T[idx] = __float2half_rn(W2[k * Dn + n]);
    }
    if (idx < Mrows) {                      // zero heads pad cols 252..255
        __half2* p = (__half2*)&heads[(size_t)idx * Dn + 252];
        p[0] = __half2half2(__float2half_rn(0.f));
        p[1] = __half2half2(__float2half_rn(0.f));
    }
    // x -> fp16 (float2 -> half2), grid-stride
    const float2* x2 = (const float2*)x;
    __half2* xh2 = (__half2*)xh;
    for (int i = idx; i < Mrows * Dn / 2; i += 262144)
        xh2[i] = __float22half2_rn(x2[i]);
}

// ---------------------------------------------------------------------------
// fp16 tensor-core GEMM: C[M,N] = A[M,K] @ B'[N,K]^T  (+ epilogue)
// A row-major [M][K] fp16; B pre-transposed [N][K] fp16.
// BM=128, BN=128, BK=32; 256 threads = 8 warps (2m x 4n), warp tile 64x32.
// m16n8k16 fp16 MMA, fp32 accumulate. 3-stage cp.async pipeline.
// MODE 0: fp32 out; MODE 1: relu(acc+bias) -> fp16 out; MODE 2: acc+bias+resid fp32
// ---------------------------------------------------------------------------
#define PA32  28                       // smem row pitch in b32 (56 halves, 112B)
#define STG32 (256 * PA32)             // A(128 rows) + B(128 rows) = 7168 b32
#define GEMM_SMEM (3 * STG32 * 4)      // 86016 B

template<int MODE>
__global__ __launch_bounds__(256) void gemm_f16k(
    const __half* __restrict__ A, const __half* __restrict__ B, void* __restrict__ Cv,
    const float* __restrict__ bias, const float* __restrict__ resid,
    int M, int N, int K)
{
    extern __shared__ uint32_t sm[];
    uint32_t sbase = (uint32_t)__cvta_generic_to_shared(sm);

    int tid  = threadIdx.x;
    int lane = tid & 31, wid = tid >> 5;
    int wm = wid & 1, wn = wid >> 1;
    int bm = blockIdx.y * 128, bn = blockIdx.x * 128;
    int r  = lane >> 2, cq = lane & 3;

    float acc[4][4][4];
#pragma unroll
    for (int mf = 0; mf < 4; mf++)
#pragma unroll
        for (int nf = 0; nf < 4; nf++)
#pragma unroll
            for (int i = 0; i < 4; i++) acc[mf][nf][i] = 0.0f;

    // loader coords: 512 16B-chunks for A (128 rows x 4), same for B; 2+2 per thread
    int c_r0 = tid >> 2;               // 0..63
    int c_r1 = c_r0 + 64;              // 64..127
    int c_k  = (tid & 3) * 8;          // half offset within row: 0,8,16,24

    const __half* Ag0 = A + (size_t)(bm + c_r0) * K + c_k;
    const __half* Ag1 = A + (size_t)(bm + c_r1) * K + c_k;
    const __half* Bg0 = B + (size_t)(bn + c_r0) * K + c_k;
    const __half* Bg1 = B + (size_t)(bn + c_r1) * K + c_k;

    uint32_t sA0 = sbase + (c_r0 * 56 + c_k) * 2;
    uint32_t sA1 = sbase + (c_r1 * 56 + c_k) * 2;
    uint32_t sB0 = sbase + (128 * 56 + c_r0 * 56 + c_k) * 2;
    uint32_t sB1 = sbase + (128 * 56 + c_r1 * 56 + c_k) * 2;

    int nk = K >> 5;

    // prologue: stages 0,1
#pragma unroll
    for (int p = 0; p < 2; p++) {
        uint32_t off = p * (STG32 * 4);
        cp16(sA0 + off, Ag0 + p * 32);
        cp16(sA1 + off, Ag1 + p * 32);
        cp16(sB0 + off, Bg0 + p * 32);
        cp16(sB1 + off, Bg1 + p * 32);
        asm volatile("cp.async.commit_group;" ::: "memory");
    }

    for (int it = 0; it < nk; it++) {
        int s = it % 3;
        asm volatile("cp.async.wait_group 1;" ::: "memory");
        __syncthreads();

        int nt = it + 2;
        if (nt < nk) {
            uint32_t off = (nt % 3) * (STG32 * 4);
            cp16(sA0 + off, Ag0 + nt * 32);
            cp16(sA1 + off, Ag1 + nt * 32);
            cp16(sB0 + off, Bg0 + nt * 32);
            cp16(sB1 + off, Bg1 + nt * 32);
        }
        asm volatile("cp.async.commit_group;" ::: "memory");

        const uint32_t* As32 = sm + s * STG32;
        const uint32_t* Bs32 = As32 + 128 * PA32;
#pragma unroll
        for (int kk2 = 0; kk2 < 16; kk2 += 8) {    // two k16 steps (b32 offsets 0, 8)
            uint32_t a[4][4], b[4][2];
#pragma unroll
            for (int mf = 0; mf < 4; mf++) {
                int ar = (wm * 64 + mf * 16 + r) * PA32 + kk2 + cq;
                a[mf][0] = As32[ar];
                a[mf][1] = As32[ar + 8 * PA32];
                a[mf][2] = As32[ar + 4];
                a[mf][3] = As32[ar + 8 * PA32 + 4];
            }
#pragma unroll
            for (int nf = 0; nf < 4; nf++) {
                int bc = (wn * 32 + nf * 8 + r) * PA32 + kk2 + cq;
                b[nf][0] = Bs32[bc];
                b[nf][1] = Bs32[bc + 4];
            }
#pragma unroll
            for (int mf = 0; mf < 4; mf++)
#pragma unroll
                for (int nf = 0; nf < 4; nf++)
                    mma_f16(acc[mf][nf], a[mf], b[nf]);
        }
    }

#pragma unroll
    for (int mf = 0; mf < 4; mf++) {
#pragma unroll
        for (int nf = 0; nf < 4; nf++) {
            int row = bm + wm * 64 + mf * 16 + r;
            int col = bn + wn * 32 + nf * 8 + cq * 2;
            size_t o0 = (size_t)row * N + col;
            size_t o1 = (size_t)(row + 8) * N + col;
            float v0 = acc[mf][nf][0], v1 = acc[mf][nf][1];
            float v2 = acc[mf][nf][2], v3 = acc[mf][nf][3];
            if (MODE == 1) {
                float b0 = bias[col], b1 = bias[col + 1];
                v0 = fmaxf(v0 + b0, 0.f); v1 = fmaxf(v1 + b1, 0.f);
                v2 = fmaxf(v2 + b0, 0.f); v3 = fmaxf(v3 + b1, 0.f);
                __half* C = (__half*)Cv;
                *(__half2*)&C[o0] = __floats2half2_rn(v0, v1);
                *(__half2*)&C[o1] = __floats2half2_rn(v2, v3);
            } else {
                if (MODE == 2) {
                    float b0 = bias[col], b1 = bias[col + 1];
                    float2 r0 = *(const float2*)(resid + o0);
                    float2 r1 = *(const float2*)(resid + o1);
                    v0 += b0 + r0.x; v1 += b1 + r0.y;
                    v2 += b0 + r1.x; v3 += b1 + r1.y;
                }
                float* C = (float*)Cv;
                *(float2*)&C[o0] = make_float2(v0, v1);
                *(float2*)&C[o1] = make_float2(v2, v3);
            }
        }
    }
}

// ---------------------------------------------------------------------------
// Fused causal attention (round-7 core; epilogue writes fp16 heads).
// One block per (b, h, mtile), 512 threads / 16 warps, 177KB smem.
// ---------------------------------------------------------------------------
#define LQ  52
#define LVF 56
#define LP  132
#define ATTN_SMEM ((128*LQ + 256*LQ + 128*LVF + 128*LP) * 4 + (128 + 128 + 16) * 4)

__global__ __launch_bounds__(512) void attn_fused(const float* __restrict__ qkv,
                                                  __half* __restrict__ heads) {
    extern __shared__ uint32_t smu[];
    uint32_t* Qs = smu;
    uint32_t* Ks = Qs + 128 * LQ;
    uint32_t* Vs = Ks + 256 * LQ;
    uint32_t* Ps = Vs + 128 * LVF;
    float* lrow = (float*)(Ps + 128 * LP);
    float* m0s  = lrow + 128;
    float* red  = m0s + 128;

    int bh = blockIdx.x;
    int b = bh / Hn, h = bh - b * Hn;
    int mtile = blockIdx.y;
    int bm = mtile * 128;
    int nkeys = bm + 128;

    int tid = threadIdx.x, lane = tid & 31, wid = tid >> 5;
    int r = lane >> 2, cq = lane & 3;
    const float scale = rsqrtf(42.0f);
    const float* base = qkv + (size_t)b * Sn * NQKVP;

    for (int idx = tid; idx < 128 * 48; idx += 512) {
        int rr = idx / 48, c = idx - rr * 48;
        float v = (c < HSn) ? base[(size_t)(bm + rr) * NQKVP + h * HSn + c] * scale : 0.f;
        Qs[rr * LQ + c] = f2tf(v);
    }
    for (int idx = tid; idx < nkeys * 48; idx += 512) {
        int rr = idx / 48, c = idx - rr * 48;
        float v = (c < HSn) ? base[(size_t)rr * NQKVP + HC + h * HSn + c] : 0.f;
        Ks[rr * LQ + c] = f2tf(v);
    }
    if (tid < 128) lrow[tid] = 0.f;
    __syncthreads();

    float kn = 0.f;
    for (int rr = tid; rr < nkeys; rr += 512) {
        float s = 0.f;
#pragma unroll
        for (int c = 0; c < HSn; c++) {
            float v = __uint_as_float(Ks[rr * LQ + c]);
            s = fmaf(v, v, s);
        }
        kn = fmaxf(kn, s);
    }
#pragma unroll
    for (int off = 16; off > 0; off >>= 1)
        kn = fmaxf(kn, __shfl_xor_sync(0xffffffffu, kn, off));
    if (lane == 0) red[wid] = kn;
    __syncthreads();
    float kmax2 = red[0];
#pragma unroll
    for (int i = 1; i < 16; i++) kmax2 = fmaxf(kmax2, red[i]);
    if (tid < 128) {
        float qn = 0.f;
#pragma unroll
        for (int c = 0; c < HSn; c++) {
            float v = __uint_as_float(Qs[tid * LQ + c]);
            qn = fmaf(v, v, qn);
        }
        m0s[tid] = sqrtf(qn * kmax2);
    }

    float oacc[3][4];
#pragma unroll
    for (int nf = 0; nf < 3; nf++)
#pragma unroll
        for (int i = 0; i < 4; i++) oacc[nf][i] = 0.f;

    int wm = wid & 3, wn = wid >> 2;
    int pm = wid & 7, pn = wid >> 3;

    for (int kc = 0; kc <= mtile; kc++) {
        __syncthreads();

        for (int idx = tid; idx < 128 * 48; idx += 512) {
            int rr = idx / 48, c = idx - rr * 48;
            float v = (c < HSn)
                ? base[(size_t)(kc * 128 + rr) * NQKVP + 2 * HC + h * HSn + c] : 0.f;
            Vs[rr * LVF + c] = f2tf(v);
        }

        float sacc[2][4][4];
#pragma unroll
        for (int mf = 0; mf < 2; mf++)
#pragma unroll
            for (int nf = 0; nf < 4; nf++)
#pragma unroll
                for (int i = 0; i < 4; i++) sacc[mf][nf][i] = 0.f;

#pragma unroll
        for (int kk = 0; kk < 48; kk += 8) {
            uint32_t a[2][4], bf[4][2];
#pragma unroll
            for (int mf = 0; mf < 2; mf++) {
                int ar = (wm * 32 + mf * 16 + r) * LQ + kk + cq;
                a[mf][0] = Qs[ar];
                a[mf][1] = Qs[ar + 8 * LQ];
                a[mf][2] = Qs[ar + 4];
                a[mf][3] = Qs[ar + 8 * LQ + 4];
            }
#pragma unroll
            for (int nf = 0; nf < 4; nf++) {
                int bc = (kc * 128 + wn * 32 + nf * 8 + r) * LQ + kk + cq;
                bf[nf][0] = Ks[bc];
                bf[nf][1] = Ks[bc + 4];
            }
#pragma unroll
            for (int mf = 0; mf < 2; mf++)
#pragma unroll
                for (int nf = 0; nf < 4; nf++)
                    mma_tf32(sacc[mf][nf], a[mf], bf[nf]);
        }

#pragma unroll
        for (int mf = 0; mf < 2; mf++) {
            int lr0 = wm * 32 + mf * 16 + r;
            int lr1 = lr0 + 8;
            int gr0 = bm + lr0, gr1 = bm + lr1;
            float m00 = m0s[lr0], m01 = m0s[lr1];
            float rs0 = 0.f, rs1 = 0.f;
#pragma unroll
            for (int nf = 0; nf < 4; nf++) {
                int lc = wn * 32 + nf * 8 + cq * 2;
                int gc = kc * 128 + lc;
                float p00 = (gc     <= gr0) ? __expf(sacc[mf][nf][0] - m00) : 0.f;
                float p01 = (gc + 1 <= gr0) ? __expf(sacc[mf][nf][1] - m00) : 0.f;
                float p10 = (gc     <= gr1) ? __expf(sacc[mf][nf][2] - m01) : 0.f;
                float p11 = (gc + 1 <= gr1) ? __expf(sacc[mf][nf][3] - m01) : 0.f;
                rs0 += p00 + p01;
                rs1 += p10 + p11;
                *(uint2*)&Ps[lr0 * LP + lc] = make_uint2(f2tf(p00), f2tf(p01));
                *(uint2*)&Ps[lr1 * LP + lc] = make_uint2(f2tf(p10), f2tf(p11));
            }
            rs0 += __shfl_xor_sync(0xffffffffu, rs0, 1);
            rs0 += __shfl_xor_sync(0xffffffffu, rs0, 2);
            rs1 += __shfl_xor_sync(0xffffffffu, rs1, 1);
            rs1 += __shfl_xor_sync(0xffffffffu, rs1, 2);
            if (cq == 0) {
                atomicAdd(&lrow[lr0], rs0);
                atomicAdd(&lrow[lr1], rs1);
            }
        }
        __syncthreads();

#pragma unroll
        for (int kk = 0; kk < 128; kk += 8) {
            uint32_t a[4];
            int ar = (pm * 16 + r) * LP + kk + cq;
            a[0] = Ps[ar];
            a[1] = Ps[ar + 8 * LP];
            a[2] = Ps[ar + 4];
            a[3] = Ps[ar + 8 * LP + 4];
            uint32_t bf[3][2];
#pragma unroll
            for (int nf = 0; nf < 3; nf++) {
                int bc = (kk + cq) * LVF + pn * 24 + nf * 8 + r;
                bf[nf][0] = Vs[bc];
                bf[nf][1] = Vs[bc + 4 * LVF];
            }
#pragma unroll
            for (int nf = 0; nf < 3; nf++)
                mma_tf32(oacc[nf], a, bf[nf]);
        }
    }
    __syncthreads();

    int lr0 = pm * 16 + r;
    int lr1 = lr0 + 8;
    float li0 = 1.0f / lrow[lr0];
    float li1 = 1.0f / lrow[lr1];
#pragma unroll
    for (int nf = 0; nf < 3; nf++) {
        int col = pn * 24 + nf * 8 + cq * 2;
        if (col < HSn) {
            *(__half2*)&heads[(size_t)(b * Sn + bm + lr0) * Dn + h * HSn + col] =
                __floats2half2_rn(oacc[nf][0] * li0, oacc[nf][1] * li0);
            *(__half2*)&heads[(size_t)(b * Sn + bm + lr1) * Dn + h * HSn + col] =
                __floats2half2_rn(oacc[nf][2] * li1, oacc[nf][3] * li1);
        }
    }
}

// ---------------------------------------------------------------------------
// LayerNorm over last dim (256): one warp per row. Optional fp16 copy.
// ---------------------------------------------------------------------------
__global__ void ln_kernel(const float* __restrict__ in, const float* __restrict__ g,
                          const float* __restrict__ bb, float* __restrict__ out,
                          __half* __restrict__ outH) {
    int row = blockIdx.x * blockDim.y + threadIdx.y;
    int lane = threadIdx.x;
    const float4* x = (const float4*)(in + (size_t)row * Dn);
    float4 a = x[lane];
    float4 c = x[lane + 32];
    float s  = a.x + a.y + a.z + a.w + c.x + c.y + c.z + c.w;
    float ss = a.x*a.x + a.y*a.y + a.z*a.z + a.w*a.w
             + c.x*c.x + c.y*c.y + c.z*c.z + c.w*c.w;
#pragma unroll
    for (int off = 16; off > 0; off >>= 1) {
        s  += __shfl_xor_sync(0xffffffffu, s,  off);
        ss += __shfl_xor_sync(0xffffffffu, ss, off);
    }
    float mean = s * (1.0f / 256.0f);
    float var  = ss * (1.0f / 256.0f) - mean * mean;
    float rstd = rsqrtf(var + 1e-5f);
    float4 g1 = ((const float4*)g)[lane],  g2 = ((const float4*)g)[lane + 32];
    float4 b1 = ((const float4*)bb)[lane], b2 = ((const float4*)bb)[lane + 32];
    float4 r1, r2;
    r1.x = (a.x - mean) * rstd * g1.x + b1.x;
    r1.y = (a.y - mean) * rstd * g1.y + b1.y;
    r1.z = (a.z - mean) * rstd * g1.z + b1.z;
    r1.w = (a.w - mean) * rstd * g1.w + b1.w;
    r2.x = (c.x - mean) * rstd * g2.x + b2.x;
    r2.y = (c.y - mean) * rstd * g2.y + b2.y;
    r2.z = (c.z - mean) * rstd * g2.z + b2.z;
    r2.w = (c.w - mean) * rstd * g2.w + b2.w;
    float4* o4 = (float4*)(out + (size_t)row * Dn);
    o4[lane] = r1;
    o4[lane + 32] = r2;
    if (outH) {
        __half2* t2 = (__half2*)(outH + (size_t)row * Dn);
        t2[lane * 2]          = __floats2half2_rn(r1.x, r1.y);
        t2[lane * 2 + 1]      = __floats2half2_rn(r1.z, r1.w);
        t2[(lane + 32) * 2]     = __floats2half2_rn(r2.x, r2.y);
        t2[(lane + 32) * 2 + 1] = __floats2half2_rn(r2.z, r2.w);
    }
}

// ---------------------------------------------------------------------------
// Launch
// ---------------------------------------------------------------------------
extern "C" void kernel_launch(void* const* d_in, const int* in_sizes, int n_in,
                              void* d_out, int out_size) {
    const float* x     = (const float*)d_in[0];
    const float* Wq    = (const float*)d_in[1];
    const float* Wk    = (const float*)d_in[2];
    const float* Wv    = (const float*)d_in[3];
    const float* Wproj = (const float*)d_in[4];
    const float* bproj = (const float*)d_in[5];
    const float* ln1_g = (const float*)d_in[6];
    const float* ln1_b = (const float*)d_in[7];
    const float* W1    = (const float*)d_in[8];
    const float* b1    = (const float*)d_in[9];
    const float* W2    = (const float*)d_in[10];
    const float* b2    = (const float*)d_in[11];
    const float* ln2_g = (const float*)d_in[12];
    const float* ln2_b = (const float*)d_in[13];
    float* out = (float*)d_out;

    float *qkv, *res1, *ln1, *res2;
    __half *xh, *heads, *ln1h, *ff1, *wqkvT, *wprojT, *w1T, *w2T;
    cudaGetSymbolAddress((void**)&qkv,    g_qkv);
    cudaGetSymbolAddress((void**)&xh,     g_xh);
    cudaGetSymbolAddress((void**)&heads,  g_heads);
    cudaGetSymbolAddress((void**)&res1,   g_res1);
    cudaGetSymbolAddress((void**)&ln1,    g_ln1);
    cudaGetSymbolAddress((void**)&ln1h,   g_ln1h);
    cudaGetSymbolAddress((void**)&ff1,    g_ff1);
    cudaGetSymbolAddress((void**)&res2,   g_res2);
    cudaGetSymbolAddress((void**)&wqkvT,  g_wqkvT);
    cudaGetSymbolAddress((void**)&wprojT, g_wprojT);
    cudaGetSymbolAddress((void**)&w1T,    g_w1T);
    cudaGetSymbolAddress((void**)&w2T,    g_w2T);

    cudaFuncSetAttribute(attn_fused, cudaFuncAttributeMaxDynamicSharedMemorySize, ATTN_SMEM);
    cudaFuncSetAttribute(gemm_f16k<0>, cudaFuncAttributeMaxDynamicSharedMemorySize, GEMM_SMEM);
    cudaFuncSetAttribute(gemm_f16k<1>, cudaFuncAttributeMaxDynamicSharedMemorySize, GEMM_SMEM);
    cudaFuncSetAttribute(gemm_f16k<2>, cudaFuncAttributeMaxDynamicSharedMemorySize, GEMM_SMEM);

    // 1. pack: weights -> fp16 transposed, x -> fp16, zero heads pads
    pack_kernel<<<1024, 256>>>(x, Wq, Wk, Wv, Wproj, W1, W2,
                               wqkvT, wprojT, w1T, w2T, xh, heads);
    // 2. QKV GEMM -> fp32 qkv
    gemm_f16k<0><<<dim3(NQKVP / 128, Mrows / 128), 256, GEMM_SMEM>>>(
        xh, wqkvT, qkv, nullptr, nullptr, Mrows, NQKVP, Dn);
    // 3. fused attention -> heads (fp16)
    attn_fused<<<dim3(BHn, 2), 512, ATTN_SMEM>>>(qkv, heads);
    // 4. proj + bias + residual(x) -> res1 (fp32)
    gemm_f16k<2><<<dim3(Dn / 128, Mrows / 128), 256, GEMM_SMEM>>>(
        heads, wprojT, res1, bproj, x, Mrows, Dn, Dn);
    // 5. LN1 -> ln1 (fp32) + ln1h (fp16)
    ln_kernel<<<Mrows / 8, dim3(32, 8)>>>(res1, ln1_g, ln1_b, ln1, ln1h);
    // 6. FFN1 + ReLU -> ff1 (fp16)
    gemm_f16k<1><<<dim3(DFFn / 128, Mrows / 128), 256, GEMM_SMEM>>>(
        ln1h, w1T, ff1, b1, nullptr, Mrows, DFFn, Dn);
    // 7. FFN2 + bias + residual(ln1) -> res2 (fp32)
    gemm_f16k<2><<<dim3(Dn / 128, Mrows / 128), 256, GEMM_SMEM>>>(
        ff1, w2T, res2, b2, ln1, Mrows, Dn, DFFn);
    // 8. LN2 -> output
    ln_kernel<<<Mrows / 8, dim3(32, 8)>>>(res2, ln2_g, ln2_b, out, nullptr);
}

// round 12
// speedup vs baseline: 1.5623x; 1.1254x over previous
#include <cuda_runtime.h>
#include <cuda_fp16.h>
#include <math.h>
#include <stdint.h>

// Problem constants
#define Bn    128
#define Sn    256
#define Dn    256
#define Hn    6
#define HSn   42
#define HC    252
#define NQKVP 768
#define DFFn  1024
#define Mrows 32768
#define BHn   (Bn*Hn)

// ---------------------------------------------------------------------------
// Scratch (allocation-free: __device__ globals)
// ---------------------------------------------------------------------------
__device__ float  g_qkv  [(size_t)Mrows * NQKVP]; // fp32 q|k|v (attention input)
__device__ __half g_xh   [(size_t)Mrows * Dn];    // x as fp16
__device__ __half g_heads[(size_t)Mrows * Dn];    // head_cat fp16 (cols 252..255 = 0)
__device__ float  g_res1 [(size_t)Mrows * Dn];
__device__ float  g_ln1  [(size_t)Mrows * Dn];    // LN1 fp32 (resid use)
__device__ __half g_ln1h [(size_t)Mrows * Dn];    // LN1 fp16 (GEMM use)
__device__ __half g_ff1  [(size_t)Mrows * DFFn];  // relu(ffn1) fp16
__device__ float  g_res2 [(size_t)Mrows * Dn];
// Weights, TRANSPOSED [N][K], fp16:
__device__ __half g_wqkvT [NQKVP * Dn];
__device__ __half g_wprojT[Dn * Dn];
__device__ __half g_w1T   [DFFn * Dn];
__device__ __half g_w2T   [Dn * DFFn];

// ---------------------------------------------------------------------------
// helpers
// ---------------------------------------------------------------------------
__device__ __forceinline__ uint32_t f2tf(float f) {
    uint32_t u;
    asm("cvt.rna.tf32.f32 %0, %1;" : "=r"(u) : "f"(f));
    return u;
}
__device__ __forceinline__ void mma_tf32(float c[4], const uint32_t a[4], const uint32_t b[2]) {
    asm volatile(
        "mma.sync.aligned.m16n8k8.row.col.f32.tf32.tf32.f32 "
        "{%0,%1,%2,%3}, {%4,%5,%6,%7}, {%8,%9}, {%0,%1,%2,%3};"
        : "+f"(c[0]), "+f"(c[1]), "+f"(c[2]), "+f"(c[3])
        : "r"(a[0]), "r"(a[1]), "r"(a[2]), "r"(a[3]), "r"(b[0]), "r"(b[1]));
}
__device__ __forceinline__ void mma_f16(float c[4], const uint32_t a[4], const uint32_t b[2]) {
    asm volatile(
        "mma.sync.aligned.m16n8k16.row.col.f32.f16.f16.f32 "
        "{%0,%1,%2,%3}, {%4,%5,%6,%7}, {%8,%9}, {%0,%1,%2,%3};"
        : "+f"(c[0]), "+f"(c[1]), "+f"(c[2]), "+f"(c[3])
        : "r"(a[0]), "r"(a[1]), "r"(a[2]), "r"(a[3]), "r"(b[0]), "r"(b[1]));
}
__device__ __forceinline__ void cp16(uint32_t saddr, const void* g) {
    asm volatile("cp.async.ca.shared.global [%0], [%1], 16;" :: "r"(saddr), "l"(g));
}
__device__ __forceinline__ void ldsm4(uint32_t& r0, uint32_t& r1, uint32_t& r2, uint32_t& r3,
                                      uint32_t addr) {
    asm volatile("ldmatrix.sync.aligned.m8n8.x4.shared.b16 {%0,%1,%2,%3}, [%4];"
        : "=r"(r0), "=r"(r1), "=r"(r2), "=r"(r3) : "r"(addr));
}

// ---------------------------------------------------------------------------
// Pack: weights -> fp16 transposed [N][K]; x -> fp16; zero heads pad cols.
// ---------------------------------------------------------------------------
__global__ void pack_kernel(const float* __restrict__ x,
                            const float* __restrict__ Wq, const float* __restrict__ Wk,
                            const float* __restrict__ Wv, const float* __restrict__ Wproj,
                            const float* __restrict__ W1, const float* __restrict__ W2,
                            __half* __restrict__ wqkvT, __half* __restrict__ wprojT,
                            __half* __restrict__ w1T, __half* __restrict__ w2T,
                            __half* __restrict__ xh, __half* __restrict__ heads) {
    int idx = blockIdx.x * 256 + threadIdx.x;
    if (idx < NQKVP * Dn) {                 // wqkvT[j][d], j = output col
        int j = idx >> 8, d = idx & 255;
        float val = 0.0f;
        if (j < 756) {
            int which = j / HC;
            int rr = j - which * HC;
            int h = rr / HSn, c = rr - h * HSn;
            const float* W = (which == 0) ? Wq : (which == 1) ? Wk : Wv;
            val = W[(h * Dn + d) * HSn + c];
        }
        wqkvT[idx] = __float2half_rn(val);
    }
    if (idx < Dn * Dn) {                    // wprojT[n][k]
        int n = idx >> 8, k = idx & 255;
        wprojT[idx] = __float2half_rn((k < HC) ? Wproj[k * Dn + n] : 0.0f);
    }
    {                                       // w1T[n][k]
        int n = idx >> 8, k = idx & 255;
        w1T[idx] = __float2half_rn(W1[k * DFFn + n]);
    }
    {                                       // w2T[n][k]
        int n = idx >> 10, k = idx & 1023;
        w2T[idx] = __float2half_rn(W2[k * Dn + n]);
    }
    if (idx < Mrows) {                      // zero heads pad cols 252..255
        __half2* p = (__half2*)&heads[(size_t)idx * Dn + 252];
        p[0] = __half2half2(__float2half_rn(0.f));
        p[1] = __half2half2(__float2half_rn(0.f));
    }
    const float2* x2 = (const float2*)x;
    __half2* xh2 = (__half2*)xh;
    for (int i = idx; i < Mrows * Dn / 2; i += 262144)
        xh2[i] = __float22half2_rn(x2[i]);
}

// ---------------------------------------------------------------------------
// fp16 tensor-core GEMM v2: C[M,N] = A[M,K] @ B'[N,K]^T  (+ epilogue)
// A row-major [M][K] fp16; B pre-transposed [N][K] fp16.
// BM=128, BN=128, BK=64; 256 threads = 8 warps (2m x 4n), warp tile 64x32.
// m16n8k16 fp16 MMA, fp32 accumulate. 2-stage cp.async pipeline, ldmatrix
// fragment loads (12 LDSM per stage vs 48 scalar LDS before).
// MODE 0: fp32 out; MODE 1: relu(acc+bias) -> fp16 out; MODE 2: acc+bias+resid fp32
// ---------------------------------------------------------------------------
#define PH    72                        // smem row pitch in halves (64 + 8)
#define STG32 (256 * (PH / 2))          // per-stage b32 words: 256 rows * 36 = 9216
#define GEMM_SMEM (2 * STG32 * 4)       // 73728 B

template<int MODE>
__global__ __launch_bounds__(256, 2) void gemm_f16k(
    const __half* __restrict__ A, const __half* __restrict__ B, void* __restrict__ Cv,
    const float* __restrict__ bias, const float* __restrict__ resid,
    int M, int N, int K)
{
    extern __shared__ uint32_t sm[];
    uint32_t sbase = (uint32_t)__cvta_generic_to_shared(sm);

    int tid  = threadIdx.x;
    int lane = tid & 31, wid = tid >> 5;
    int wm = wid & 1, wn = wid >> 1;
    int bm = blockIdx.y * 128, bn = blockIdx.x * 128;
    int r  = lane >> 2, cq = lane & 3;

    float acc[4][4][4];
#pragma unroll
    for (int mf = 0; mf < 4; mf++)
#pragma unroll
        for (int nf = 0; nf < 4; nf++)
#pragma unroll
            for (int i = 0; i < 4; i++) acc[mf][nf][i] = 0.0f;

    // loader: 1024 16B-chunks per stage for A (128 rows x 8), same for B; 4+4/thread
    int l_row = tid >> 3;                // 0..31 (+32*i)
    int l_ko  = (tid & 7) * 8;           // half offset 0..56
    const __half* Ag0 = A + (size_t)(bm + l_row) * K + l_ko;
    const __half* Bg0 = B + (size_t)(bn + l_row) * K + l_ko;
    uint32_t sA0 = sbase + (l_row * PH + l_ko) * 2;
    uint32_t sB0 = sbase + ((128 + l_row) * PH + l_ko) * 2;

    // ldmatrix lane addressing
    int l8 = lane & 7, lm = lane >> 3;   // octet row, matrix index 0..3
    int arow = (lm & 1) * 8 + l8;        // +8 for matrices 1,3
    int akof = (lm >> 1) * 8;            // +8 halves for matrices 2,3
    uint32_t aAddr[4], bAddr[2];
#pragma unroll
    for (int mf = 0; mf < 4; mf++)
        aAddr[mf] = sbase + ((wm * 64 + mf * 16 + arow) * PH + akof) * 2;
#pragma unroll
    for (int p = 0; p < 2; p++)
        bAddr[p] = sbase + ((128 + wn * 32 + p * 16 + arow) * PH + akof) * 2;

    int nk = K >> 6;

    // prologue: stage 0
#pragma unroll
    for (int i = 0; i < 4; i++) {
        cp16(sA0 + i * (32 * PH * 2), Ag0 + (size_t)(32 * i) * K);
        cp16(sB0 + i * (32 * PH * 2), Bg0 + (size_t)(32 * i) * K);
    }
    asm volatile("cp.async.commit_group;" ::: "memory");

    for (int it = 0; it < nk; it++) {
        uint32_t soff = (uint32_t)(it & 1) * (STG32 * 4);
        asm volatile("cp.async.wait_group 0;" ::: "memory");
        __syncthreads();

        int nt = it + 1;
        if (nt < nk) {
            uint32_t off2 = (uint32_t)(nt & 1) * (STG32 * 4);
            const __half* Agn = Ag0 + (size_t)nt * 64;
            const __half* Bgn = Bg0 + (size_t)nt * 64;
#pragma unroll
            for (int i = 0; i < 4; i++) {
                cp16(sA0 + off2 + i * (32 * PH * 2), Agn + (size_t)(32 * i) * K);
                cp16(sB0 + off2 + i * (32 * PH * 2), Bgn + (size_t)(32 * i) * K);
            }
        }
        asm volatile("cp.async.commit_group;" ::: "memory");

#pragma unroll
        for (int kk = 0; kk < 64; kk += 16) {
            uint32_t a[4][4], b[4][2];
#pragma unroll
            for (int mf = 0; mf < 4; mf++)
                ldsm4(a[mf][0], a[mf][1], a[mf][2], a[mf][3], aAddr[mf] + soff + kk * 2);
#pragma unroll
            for (int p = 0; p < 2; p++)
                ldsm4(b[2*p][0], b[2*p+1][0], b[2*p][1], b[2*p+1][1],
                      bAddr[p] + soff + kk * 2);
#pragma unroll
            for (int mf = 0; mf < 4; mf++)
#pragma unroll
                for (int nf = 0; nf < 4; nf++)
                    mma_f16(acc[mf][nf], a[mf], b[nf]);
        }
    }

#pragma unroll
    for (int mf = 0; mf < 4; mf++) {
#pragma unroll
        for (int nf = 0; nf < 4; nf++) {
            int row = bm + wm * 64 + mf * 16 + r;
            int col = bn + wn * 32 + nf * 8 + cq * 2;
            size_t o0 = (size_t)row * N + col;
            size_t o1 = (size_t)(row + 8) * N + col;
            float v0 = acc[mf][nf][0], v1 = acc[mf][nf][1];
            float v2 = acc[mf][nf][2], v3 = acc[mf][nf][3];
            if (MODE == 1) {
                float b0 = bias[col], b1 = bias[col + 1];
                v0 = fmaxf(v0 + b0, 0.f); v1 = fmaxf(v1 + b1, 0.f);
                v2 = fmaxf(v2 + b0, 0.f); v3 = fmaxf(v3 + b1, 0.f);
                __half* C = (__half*)Cv;
                *(__half2*)&C[o0] = __floats2half2_rn(v0, v1);
                *(__half2*)&C[o1] = __floats2half2_rn(v2, v3);
            } else {
                if (MODE == 2) {
                    float b0 = bias[col], b1 = bias[col + 1];
                    float2 r0 = *(const float2*)(resid + o0);
                    float2 r1 = *(const float2*)(resid + o1);
                    v0 += b0 + r0.x; v1 += b1 + r0.y;
                    v2 += b0 + r1.x; v3 += b1 + r1.y;
                }
                float* C = (float*)Cv;
                *(float2*)&C[o0] = make_float2(v0, v1);
                *(float2*)&C[o1] = make_float2(v2, v3);
            }
        }
    }
}

// ---------------------------------------------------------------------------
// Fused causal attention (unchanged; epilogue writes fp16 heads).
// One block per (b, h, mtile), 512 threads / 16 warps, 177KB smem.
// ---------------------------------------------------------------------------
#define LQ  52
#define LVF 56
#define LP  132
#define ATTN_SMEM ((128*LQ + 256*LQ + 128*LVF + 128*LP) * 4 + (128 + 128 + 16) * 4)

__global__ __launch_bounds__(512) void attn_fused(const float* __restrict__ qkv,
                                                  __half* __restrict__ heads) {
    extern __shared__ uint32_t smu[];
    uint32_t* Qs = smu;
    uint32_t* Ks = Qs + 128 * LQ;
    uint32_t* Vs = Ks + 256 * LQ;
    uint32_t* Ps = Vs + 128 * LVF;
    float* lrow = (float*)(Ps + 128 * LP);
    float* m0s  = lrow + 128;
    float* red  = m0s + 128;

    int bh = blockIdx.x;
    int b = bh / Hn, h = bh - b * Hn;
    int mtile = blockIdx.y;
    int bm = mtile * 128;
    int nkeys = bm + 128;

    int tid = threadIdx.x, lane = tid & 31, wid = tid >> 5;
    int r = lane >> 2, cq = lane & 3;
    const float scale = rsqrtf(42.0f);
    const float* base = qkv + (size_t)b * Sn * NQKVP;

    for (int idx = tid; idx < 128 * 48; idx += 512) {
        int rr = idx / 48, c = idx - rr * 48;
        float v = (c < HSn) ? base[(size_t)(bm + rr) * NQKVP + h * HSn + c] * scale : 0.f;
        Qs[rr * LQ + c] = f2tf(v);
    }
    for (int idx = tid; idx < nkeys * 48; idx += 512) {
        int rr = idx / 48, c = idx - rr * 48;
        float v = (c < HSn) ? base[(size_t)rr * NQKVP + HC + h * HSn + c] : 0.f;
        Ks[rr * LQ + c] = f2tf(v);
    }
    if (tid < 128) lrow[tid] = 0.f;
    __syncthreads();

    float kn = 0.f;
    for (int rr = tid; rr < nkeys; rr += 512) {
        float s = 0.f;
#pragma unroll
        for (int c = 0; c < HSn; c++) {
            float v = __uint_as_float(Ks[rr * LQ + c]);
            s = fmaf(v, v, s);
        }
        kn = fmaxf(kn, s);
    }
#pragma unroll
    for (int off = 16; off > 0; off >>= 1)
        kn = fmaxf(kn, __shfl_xor_sync(0xffffffffu, kn, off));
    if (lane == 0) red[wid] = kn;
    __syncthreads();
    float kmax2 = red[0];
#pragma unroll
    for (int i = 1; i < 16; i++) kmax2 = fmaxf(kmax2, red[i]);
    if (tid < 128) {
        float qn = 0.f;
#pragma unroll
        for (int c = 0; c < HSn; c++) {
            float v = __uint_as_float(Qs[tid * LQ + c]);
            qn = fmaf(v, v, qn);
        }
        m0s[tid] = sqrtf(qn * kmax2);
    }

    float oacc[3][4];
#pragma unroll
    for (int nf = 0; nf < 3; nf++)
#pragma unroll
        for (int i = 0; i < 4; i++) oacc[nf][i] = 0.f;

    int wm = wid & 3, wn = wid >> 2;
    int pm = wid & 7, pn = wid >> 3;

    for (int kc = 0; kc <= mtile; kc++) {
        __syncthreads();

        for (int idx = tid; idx < 128 * 48; idx += 512) {
            int rr = idx / 48, c = idx - rr * 48;
            float v = (c < HSn)
                ? base[(size_t)(kc * 128 + rr) * NQKVP + 2 * HC + h * HSn + c] : 0.f;
            Vs[rr * LVF + c] = f2tf(v);
        }

        float sacc[2][4][4];
#pragma unroll
        for (int mf = 0; mf < 2; mf++)
#pragma unroll
            for (int nf = 0; nf < 4; nf++)
#pragma unroll
                for (int i = 0; i < 4; i++) sacc[mf][nf][i] = 0.f;

#pragma unroll
        for (int kk = 0; kk < 48; kk += 8) {
            uint32_t a[2][4], bf[4][2];
#pragma unroll
            for (int mf = 0; mf < 2; mf++) {
                int ar = (wm * 32 + mf * 16 + r) * LQ + kk + cq;
                a[mf][0] = Qs[ar];
                a[mf][1] = Qs[ar + 8 * LQ];
                a[mf][2] = Qs[ar + 4];
                a[mf][3] = Qs[ar + 8 * LQ + 4];
            }
#pragma unroll
            for (int nf = 0; nf < 4; nf++) {
                int bc = (kc * 128 + wn * 32 + nf * 8 + r) * LQ + kk + cq;
                bf[nf][0] = Ks[bc];
                bf[nf][1] = Ks[bc + 4];
            }
#pragma unroll
            for (int mf = 0; mf < 2; mf++)
#pragma unroll
                for (int nf = 0; nf < 4; nf++)
                    mma_tf32(sacc[mf][nf], a[mf], bf[nf]);
        }

#pragma unroll
        for (int mf = 0; mf < 2; mf++) {
            int lr0 = wm * 32 + mf * 16 + r;
            int lr1 = lr0 + 8;
            int gr0 = bm + lr0, gr1 = bm + lr1;
            float m00 = m0s[lr0], m01 = m0s[lr1];
            float rs0 = 0.f, rs1 = 0.f;
#pragma unroll
            for (int nf = 0; nf < 4; nf++) {
                int lc = wn * 32 + nf * 8 + cq * 2;
                int gc = kc * 128 + lc;
                float p00 = (gc     <= gr0) ? __expf(sacc[mf][nf][0] - m00) : 0.f;
                float p01 = (gc + 1 <= gr0) ? __expf(sacc[mf][nf][1] - m00) : 0.f;
                float p10 = (gc     <= gr1) ? __expf(sacc[mf][nf][2] - m01) : 0.f;
                float p11 = (gc + 1 <= gr1) ? __expf(sacc[mf][nf][3] - m01) : 0.f;
                rs0 += p00 + p01;
                rs1 += p10 + p11;
                *(uint2*)&Ps[lr0 * LP + lc] = make_uint2(f2tf(p00), f2tf(p01));
                *(uint2*)&Ps[lr1 * LP + lc] = make_uint2(f2tf(p10), f2tf(p11));
            }
            rs0 += __shfl_xor_sync(0xffffffffu, rs0, 1);
            rs0 += __shfl_xor_sync(0xffffffffu, rs0, 2);
            rs1 += __shfl_xor_sync(0xffffffffu, rs1, 1);
            rs1 += __shfl_xor_sync(0xffffffffu, rs1, 2);
            if (cq == 0) {
                atomicAdd(&lrow[lr0], rs0);
                atomicAdd(&lrow[lr1], rs1);
            }
        }
        __syncthreads();

#pragma unroll
        for (int kk = 0; kk < 128; kk += 8) {
            uint32_t a[4];
            int ar = (pm * 16 + r) * LP + kk + cq;
            a[0] = Ps[ar];
            a[1] = Ps[ar + 8 * LP];
            a[2] = Ps[ar + 4];
            a[3] = Ps[ar + 8 * LP + 4];
            uint32_t bf[3][2];
#pragma unroll
            for (int nf = 0; nf < 3; nf++) {
                int bc = (kk + cq) * LVF + pn * 24 + nf * 8 + r;
                bf[nf][0] = Vs[bc];
                bf[nf][1] = Vs[bc + 4 * LVF];
            }
#pragma unroll
            for (int nf = 0; nf < 3; nf++)
                mma_tf32(oacc[nf], a, bf[nf]);
        }
    }
    __syncthreads();

    int lr0 = pm * 16 + r;
    int lr1 = lr0 + 8;
    float li0 = 1.0f / lrow[lr0];
    float li1 = 1.0f / lrow[lr1];
#pragma unroll
    for (int nf = 0; nf < 3; nf++) {
        int col = pn * 24 + nf * 8 + cq * 2;
        if (col < HSn) {
            *(__half2*)&heads[(size_t)(b * Sn + bm + lr0) * Dn + h * HSn + col] =
                __floats2half2_rn(oacc[nf][0] * li0, oacc[nf][1] * li0);
            *(__half2*)&heads[(size_t)(b * Sn + bm + lr1) * Dn + h * HSn + col] =
                __floats2half2_rn(oacc[nf][2] * li1, oacc[nf][3] * li1);
        }
    }
}

// ---------------------------------------------------------------------------
// LayerNorm over last dim (256): one warp per row. Optional fp16 copy.
// ---------------------------------------------------------------------------
__global__ void ln_kernel(const float* __restrict__ in, const float* __restrict__ g,
                          const float* __restrict__ bb, float* __restrict__ out,
                          __half* __restrict__ outH) {
    int row = blockIdx.x * blockDim.y + threadIdx.y;
    int lane = threadIdx.x;
    const float4* x = (const float4*)(in + (size_t)row * Dn);
    float4 a = x[lane];
    float4 c = x[lane + 32];
    float s  = a.x + a.y + a.z + a.w + c.x + c.y + c.z + c.w;
    float ss = a.x*a.x + a.y*a.y + a.z*a.z + a.w*a.w
             + c.x*c.x + c.y*c.y + c.z*c.z + c.w*c.w;
#pragma unroll
    for (int off = 16; off > 0; off >>= 1) {
        s  += __shfl_xor_sync(0xffffffffu, s,  off);
        ss += __shfl_xor_sync(0xffffffffu, ss, off);
    }
    float mean = s * (1.0f / 256.0f);
    float var  = ss * (1.0f / 256.0f) - mean * mean;
    float rstd = rsqrtf(var + 1e-5f);
    float4 g1 = ((const float4*)g)[lane],  g2 = ((const float4*)g)[lane + 32];
    float4 b1 = ((const float4*)bb)[lane], b2 = ((const float4*)bb)[lane + 32];
    float4 r1, r2;
    r1.x = (a.x - mean) * rstd * g1.x + b1.x;
    r1.y = (a.y - mean) * rstd * g1.y + b1.y;
    r1.z = (a.z - mean) * rstd * g1.z + b1.z;
    r1.w = (a.w - mean) * rstd * g1.w + b1.w;
    r2.x = (c.x - mean) * rstd * g2.x + b2.x;
    r2.y = (c.y - mean) * rstd * g2.y + b2.y;
    r2.z = (c.z - mean) * rstd * g2.z + b2.z;
    r2.w = (c.w - mean) * rstd * g2.w + b2.w;
    float4* o4 = (float4*)(out + (size_t)row * Dn);
    o4[lane] = r1;
    o4[lane + 32] = r2;
    if (outH) {
        __half2* t2 = (__half2*)(outH + (size_t)row * Dn);
        t2[lane * 2]          = __floats2half2_rn(r1.x, r1.y);
        t2[lane * 2 + 1]      = __floats2half2_rn(r1.z, r1.w);
        t2[(lane + 32) * 2]     = __floats2half2_rn(r2.x, r2.y);
        t2[(lane + 32) * 2 + 1] = __floats2half2_rn(r2.z, r2.w);
    }
}

// ---------------------------------------------------------------------------
// Launch
// ---------------------------------------------------------------------------
extern "C" void kernel_launch(void* const* d_in, const int* in_sizes, int n_in,
                              void* d_out, int out_size) {
    const float* x     = (const float*)d_in[0];
    const float* Wq    = (const float*)d_in[1];
    const float* Wk    = (const float*)d_in[2];
    const float* Wv    = (const float*)d_in[3];
    const float* Wproj = (const float*)d_in[4];
    const float* bproj = (const float*)d_in[5];
    const float* ln1_g = (const float*)d_in[6];
    const float* ln1_b = (const float*)d_in[7];
    const float* W1    = (const float*)d_in[8];
    const float* b1    = (const float*)d_in[9];
    const float* W2    = (const float*)d_in[10];
    const float* b2    = (const float*)d_in[11];
    const float* ln2_g = (const float*)d_in[12];
    const float* ln2_b = (const float*)d_in[13];
    float* out = (float*)d_out;

    float *qkv, *res1, *ln1, *res2;
    __half *xh, *heads, *ln1h, *ff1, *wqkvT, *wprojT, *w1T, *w2T;
    cudaGetSymbolAddress((void**)&qkv,    g_qkv);
    cudaGetSymbolAddress((void**)&xh,     g_xh);
    cudaGetSymbolAddress((void**)&heads,  g_heads);
    cudaGetSymbolAddress((void**)&res1,   g_res1);
    cudaGetSymbolAddress((void**)&ln1,    g_ln1);
    cudaGetSymbolAddress((void**)&ln1h,   g_ln1h);
    cudaGetSymbolAddress((void**)&ff1,    g_ff1);
    cudaGetSymbolAddress((void**)&res2,   g_res2);
    cudaGetSymbolAddress((void**)&wqkvT,  g_wqkvT);
    cudaGetSymbolAddress((void**)&wprojT, g_wprojT);
    cudaGetSymbolAddress((void**)&w1T,    g_w1T);
    cudaGetSymbolAddress((void**)&w2T,    g_w2T);

    cudaFuncSetAttribute(attn_fused, cudaFuncAttributeMaxDynamicSharedMemorySize, ATTN_SMEM);
    cudaFuncSetAttribute(gemm_f16k<0>, cudaFuncAttributeMaxDynamicSharedMemorySize, GEMM_SMEM);
    cudaFuncSetAttribute(gemm_f16k<1>, cudaFuncAttributeMaxDynamicSharedMemorySize, GEMM_SMEM);
    cudaFuncSetAttribute(gemm_f16k<2>, cudaFuncAttributeMaxDynamicSharedMemorySize, GEMM_SMEM);

    // 1. pack: weights -> fp16 transposed, x -> fp16, zero heads pads
    pack_kernel<<<1024, 256>>>(x, Wq, Wk, Wv, Wproj, W1, W2,
                               wqkvT, wprojT, w1T, w2T, xh, heads);
    // 2. QKV GEMM -> fp32 qkv
    gemm_f16k<0><<<dim3(NQKVP / 128, Mrows / 128), 256, GEMM_SMEM>>>(
        xh, wqkvT, qkv, nullptr, nullptr, Mrows, NQKVP, Dn);
    // 3. fused attention -> heads (fp16)
    attn_fused<<<dim3(BHn, 2), 512, ATTN_SMEM>>>(qkv, heads);
    // 4. proj + bias + residual(x) -> res1 (fp32)
    gemm_f16k<2><<<dim3(Dn / 128, Mrows / 128), 256, GEMM_SMEM>>>(
        heads, wprojT, res1, bproj, x, Mrows, Dn, Dn);
    // 5. LN1 -> ln1 (fp32) + ln1h (fp16)
    ln_kernel<<<Mrows / 8, dim3(32, 8)>>>(res1, ln1_g, ln1_b, ln1, ln1h);
    // 6. FFN1 + ReLU -> ff1 (fp16)
    gemm_f16k<1><<<dim3(DFFn / 128, Mrows / 128), 256, GEMM_SMEM>>>(
        ln1h, w1T, ff1, b1, nullptr, Mrows, DFFn, Dn);
    // 7. FFN2 + bias + residual(ln1) -> res2 (fp32)
    gemm_f16k<2><<<dim3(Dn / 128, Mrows / 128), 256, GEMM_SMEM>>>(
        ff1, w2T, res2, b2, ln1, Mrows, Dn, DFFn);
    // 8. LN2 -> output
    ln_kernel<<<Mrows / 8, dim3(32, 8)>>>(res2, ln2_g, ln2_b, out, nullptr);
}